// round 2
// baseline (speedup 1.0000x reference)
#include <cuda_runtime.h>

#define NN   100000
#define NE   1200000
#define NB   64
#define HID  64
#define IND  128
#define OUTD 2
#define EPSV 1e-5f

// ---------------- scratch (static device globals; no allocation) ----------------
__device__ float g_deg[NN];
__device__ float g_dinv[NN];
__device__ float g_coef[NE];
__device__ float4 g_hw4[NN * 16];    // h @ W   [N,64] as float4
__device__ float4 g_agg4[NN * 16];   // aggregate / z buffer
__device__ float4 g_h4[NN * 16];     // current activations
__device__ float g_stats[2 * HID];   // per-channel sum, sumsq
__device__ __align__(16) float g_scale[HID];
__device__ __align__(16) float g_shift[HID];
__device__ float g_pool[NB * OUTD];
__device__ float g_cnt[NB];

// ---------------- vector reductions (sm_90+) ----------------
__device__ __forceinline__ void red_add_v4(float* addr, float4 v) {
    asm volatile("red.global.add.v4.f32 [%0], {%1,%2,%3,%4};"
                 :: "l"(addr), "f"(v.x), "f"(v.y), "f"(v.z), "f"(v.w) : "memory");
}
__device__ __forceinline__ void red_add_v2(float* addr, float2 v) {
    asm volatile("red.global.add.v2.f32 [%0], {%1,%2};"
                 :: "l"(addr), "f"(v.x), "f"(v.y) : "memory");
}

// ---------------- prep ----------------
__global__ void zero_deg_k() {
    int i = blockIdx.x * 256 + threadIdx.x;
    if (i < NN) g_deg[i] = 0.f;
}

__global__ void prep_edges_k(const int* __restrict__ ei) {
    int e = blockIdx.x * 256 + threadIdx.x;
    if (e < NE) {
        int d = ei[NE + e];
        atomicAdd(&g_deg[d], 1.f);
    }
}

__global__ void dinv_k() {
    int i = blockIdx.x * 256 + threadIdx.x;
    if (i < NN) g_dinv[i] = rsqrtf(g_deg[i] + 1.f);
}

__global__ void coef_k(const int* __restrict__ ei) {
    int e = blockIdx.x * 256 + threadIdx.x;
    if (e < NE) g_coef[e] = g_dinv[ei[e]] * g_dinv[ei[NE + e]];
}

// ---------------- tiled GEMM: Y[nrows,64] = X[nrows,K] @ W[K,64] ----------------
template <int K>
__global__ void __launch_bounds__(256) gemm_64(const float* __restrict__ X,
                                               const float* __restrict__ W,
                                               float* __restrict__ Y, int nrows) {
    __shared__ float xs[64][36];   // [row][k-within-chunk], pad 4 keeps 16B alignment
    __shared__ float ws[32][64];   // [k][col]
    const int tid = threadIdx.x;
    const int row0 = blockIdx.x * 64;
    const int tx = tid & 15;       // col group
    const int ty = tid >> 4;       // row group (0..15)
    const int c0 = tx * 4;
    const int r0 = ty * 4;
    float acc[4][4] = {};

    for (int kc = 0; kc < K; kc += 32) {
        // stage X tile (64 rows x 32 k)
        #pragma unroll
        for (int it = 0; it < 2; ++it) {
            int row = (tid >> 3) + it * 32;     // 0..63
            int kk  = (tid & 7) * 4;            // 0..28
            float4 v = make_float4(0.f, 0.f, 0.f, 0.f);
            int gr = row0 + row;
            if (gr < nrows) v = *(const float4*)(X + (size_t)gr * K + kc + kk);
            *(float4*)(&xs[row][kk]) = v;
        }
        // stage W tile (32 k x 64 cols)
        #pragma unroll
        for (int it = 0; it < 2; ++it) {
            int k  = (tid >> 4) + it * 16;      // 0..31
            int cc = (tid & 15) * 4;
            *(float4*)(&ws[k][cc]) = *(const float4*)(W + (size_t)(kc + k) * 64 + cc);
        }
        __syncthreads();

        #pragma unroll
        for (int k4 = 0; k4 < 8; ++k4) {
            float4 xv[4], wv[4];
            #pragma unroll
            for (int j = 0; j < 4; ++j) xv[j] = *(const float4*)(&xs[r0 + j][k4 * 4]);
            #pragma unroll
            for (int j = 0; j < 4; ++j) wv[j] = *(const float4*)(&ws[k4 * 4 + j][c0]);
            #pragma unroll
            for (int r = 0; r < 4; ++r) {
                float xk;
                xk = xv[r].x; acc[r][0] += xk * wv[0].x; acc[r][1] += xk * wv[0].y; acc[r][2] += xk * wv[0].z; acc[r][3] += xk * wv[0].w;
                xk = xv[r].y; acc[r][0] += xk * wv[1].x; acc[r][1] += xk * wv[1].y; acc[r][2] += xk * wv[1].z; acc[r][3] += xk * wv[1].w;
                xk = xv[r].z; acc[r][0] += xk * wv[2].x; acc[r][1] += xk * wv[2].y; acc[r][2] += xk * wv[2].z; acc[r][3] += xk * wv[2].w;
                xk = xv[r].w; acc[r][0] += xk * wv[3].x; acc[r][1] += xk * wv[3].y; acc[r][2] += xk * wv[3].z; acc[r][3] += xk * wv[3].w;
            }
        }
        __syncthreads();
    }

    #pragma unroll
    for (int r = 0; r < 4; ++r) {
        int gr = row0 + r0 + r;
        if (gr < nrows)
            *(float4*)(Y + (size_t)gr * 64 + c0) =
                make_float4(acc[r][0], acc[r][1], acc[r][2], acc[r][3]);
    }
}

// ---------------- 64-dim aggregation ----------------
__global__ void __launch_bounds__(256) agg_init64_k() {
    int idx = blockIdx.x * 256 + threadIdx.x;          // over NN*16 float4s
    if (blockIdx.x == 0 && threadIdx.x < 2 * HID) g_stats[threadIdx.x] = 0.f;
    if (idx < NN * 16) {
        float d = g_dinv[idx >> 4];
        float d2 = d * d;
        float4 v = g_hw4[idx];
        v.x *= d2; v.y *= d2; v.z *= d2; v.w *= d2;
        g_agg4[idx] = v;
    }
}

__global__ void __launch_bounds__(256) agg_edges64_k(const int* __restrict__ ei) {
    int idx = blockIdx.x * 256 + threadIdx.x;          // exactly NE*16 threads
    int e = idx >> 4;
    int q = idx & 15;
    int s = ei[e];
    int d = ei[NE + e];
    float cf = g_coef[e];
    float4 v = g_hw4[s * 16 + q];
    v.x *= cf; v.y *= cf; v.z *= cf; v.w *= cf;
    red_add_v4((float*)&g_agg4[d * 16 + q], v);
}

// bias + relu + BN stats (in-place on g_agg4)
__global__ void __launch_bounds__(256) post_k(const float* __restrict__ bias) {
    float* agg = (float*)g_agg4;
    int c = threadIdx.x & 63;
    float b = bias[c];
    float s = 0.f, q = 0.f;
    int stride = gridDim.x * blockDim.x;               // multiple of 64
    for (int idx = blockIdx.x * blockDim.x + threadIdx.x; idx < NN * HID; idx += stride) {
        float z = agg[idx] + b;
        z = z > 0.f ? z : 0.f;
        agg[idx] = z;
        s += z;
        q += z * z;
    }
    __shared__ float ss[64], sq[64];
    if (threadIdx.x < 64) { ss[threadIdx.x] = 0.f; sq[threadIdx.x] = 0.f; }
    __syncthreads();
    atomicAdd(&ss[c], s);
    atomicAdd(&sq[c], q);
    __syncthreads();
    if (threadIdx.x < 64) {
        atomicAdd(&g_stats[threadIdx.x], ss[threadIdx.x]);
        atomicAdd(&g_stats[64 + threadIdx.x], sq[threadIdx.x]);
    }
}

__global__ void bn_final_k(const float* __restrict__ gamma, const float* __restrict__ beta) {
    int c = threadIdx.x;
    if (c < HID) {
        float s = g_stats[c], q = g_stats[64 + c];
        float m = s / (float)NN;
        float v = q / (float)NN - m * m;
        float istd = rsqrtf(v + EPSV);
        float sc = istd * gamma[c];
        g_scale[c] = sc;
        g_shift[c] = beta[c] - m * sc;
    }
}

template <bool RES>
__global__ void __launch_bounds__(256) norm_k() {
    int idx = blockIdx.x * 256 + threadIdx.x;          // over NN*16
    if (idx >= NN * 16) return;
    int c4 = idx & 15;
    float4 sc = ((const float4*)g_scale)[c4];
    float4 sh = ((const float4*)g_shift)[c4];
    float4 z = g_agg4[idx];
    float4 h;
    h.x = z.x * sc.x + sh.x;
    h.y = z.y * sc.y + sh.y;
    h.z = z.z * sc.z + sh.z;
    h.w = z.w * sc.w + sh.w;
    if (RES) {
        float4 o = g_h4[idx];
        h.x += o.x; h.y += o.y; h.z += o.z; h.w += o.w;
    }
    g_h4[idx] = h;
}

// ---------------- output layer (64 -> 2) ----------------
__global__ void __launch_bounds__(256) gemm_out_k(const float* __restrict__ X,
                                                  const float* __restrict__ W,
                                                  float* __restrict__ Y) {
    __shared__ float w0[64], w1[64];
    if (threadIdx.x < 64) {
        w0[threadIdx.x] = W[threadIdx.x * 2];
        w1[threadIdx.x] = W[threadIdx.x * 2 + 1];
    }
    __syncthreads();
    int warp = threadIdx.x >> 5, lane = threadIdx.x & 31;
    int row = blockIdx.x * 8 + warp;
    if (row >= NN) return;
    const float* xr = X + (size_t)row * 64;
    float x0 = xr[lane], x1 = xr[lane + 32];
    float a0 = x0 * w0[lane] + x1 * w0[lane + 32];
    float a1 = x0 * w1[lane] + x1 * w1[lane + 32];
    #pragma unroll
    for (int o = 16; o > 0; o >>= 1) {
        a0 += __shfl_down_sync(0xffffffffu, a0, o);
        a1 += __shfl_down_sync(0xffffffffu, a1, o);
    }
    if (lane == 0) {
        Y[row * 2]     = a0;
        Y[row * 2 + 1] = a1;
    }
}

__global__ void __launch_bounds__(256) agg_init2_k() {
    int i = blockIdx.x * 256 + threadIdx.x;
    if (blockIdx.x == 0) {
        if (threadIdx.x < NB * OUTD) g_pool[threadIdx.x] = 0.f;
        if (threadIdx.x < NB) g_cnt[threadIdx.x] = 0.f;
    }
    if (i < NN) {
        float d = g_dinv[i];
        float d2 = d * d;
        float2 v = ((const float2*)g_hw4)[i];
        v.x *= d2; v.y *= d2;
        ((float2*)g_agg4)[i] = v;
    }
}

__global__ void __launch_bounds__(256) agg_edges2_k(const int* __restrict__ ei) {
    int e = blockIdx.x * 256 + threadIdx.x;
    if (e < NE) {
        int s = ei[e];
        int d = ei[NE + e];
        float cf = g_coef[e];
        float2 v = ((const float2*)g_hw4)[s];
        v.x *= cf; v.y *= cf;
        red_add_v2((float*)g_agg4 + d * 2, v);
    }
}

__global__ void __launch_bounds__(256) pool_k(const int* __restrict__ batch) {
    int i = blockIdx.x * 256 + threadIdx.x;
    if (i < NN) {
        int b = batch[i];
        float2 v = ((const float2*)g_agg4)[i];
        atomicAdd(&g_pool[2 * b],     v.x);
        atomicAdd(&g_pool[2 * b + 1], v.y);
        atomicAdd(&g_cnt[b], 1.f);
    }
}

__global__ void final_k(const float* __restrict__ b_out, float* __restrict__ out) {
    int t = threadIdx.x;
    if (t < NB * OUTD) {
        int b = t >> 1, c = t & 1;
        out[t] = g_pool[t] / fmaxf(g_cnt[b], 1.f) + b_out[c];
    }
}

// ---------------- driver ----------------
extern "C" void kernel_launch(void* const* d_in, const int* in_sizes, int n_in,
                              void* d_out, int out_size) {
    const float* x       = (const float*)d_in[0];
    const float* W_in    = (const float*)d_in[1];
    const float* b_in    = (const float*)d_in[2];
    const float* W_h     = (const float*)d_in[3];
    const float* b_h     = (const float*)d_in[4];
    const float* W_out   = (const float*)d_in[5];
    const float* b_out   = (const float*)d_in[6];
    const float* bn_g    = (const float*)d_in[7];
    const float* bn_b    = (const float*)d_in[8];
    const int*   ei      = (const int*)d_in[9];      // int32: JAX x64 disabled
    const int*   bat     = (const int*)d_in[10];     // int32

    float* out = (float*)d_out;

    void *p_hw, *p_h;
    cudaGetSymbolAddress(&p_hw, g_hw4);
    cudaGetSymbolAddress(&p_h, g_h4);
    float* hw = (float*)p_hw;
    float* h  = (float*)p_h;

    // prep: degrees, dinv, per-edge coefficients (reused by all 4 layers)
    zero_deg_k<<<391, 256>>>();
    prep_edges_k<<<4688, 256>>>(ei);
    dinv_k<<<391, 256>>>();
    coef_k<<<4688, 256>>>(ei);

    // layer 1: 128 -> 64
    gemm_64<IND><<<1563, 256>>>(x, W_in, hw, NN);
    agg_init64_k<<<6250, 256>>>();
    agg_edges64_k<<<75000, 256>>>(ei);
    post_k<<<1184, 256>>>(b_in);
    bn_final_k<<<1, 64>>>(bn_g, bn_b);
    norm_k<false><<<6250, 256>>>();

    // hidden layers: 64 -> 64 with residual
    for (int i = 0; i < 2; ++i) {
        gemm_64<HID><<<1563, 256>>>(h, W_h + i * HID * HID, hw, NN);
        agg_init64_k<<<6250, 256>>>();
        agg_edges64_k<<<75000, 256>>>(ei);
        post_k<<<1184, 256>>>(b_h + i * HID);
        bn_final_k<<<1, 64>>>(bn_g + (i + 1) * HID, bn_b + (i + 1) * HID);
        norm_k<true><<<6250, 256>>>();
    }

    // output layer: 64 -> 2, then global mean pool
    gemm_out_k<<<12500, 256>>>(h, W_out, hw);
    agg_init2_k<<<391, 256>>>();
    agg_edges2_k<<<4688, 256>>>(ei);
    pool_k<<<391, 256>>>(bat);
    final_k<<<1, 128>>>(b_out, out);
}

// round 3
// speedup vs baseline: 1.1847x; 1.1847x over previous
#include <cuda_runtime.h>

#define NN   100000
#define NE   1200000
#define NB   64
#define HID  64
#define IND  128
#define OUTD 2
#define EPSV 1e-5f

typedef unsigned long long u64;

// ---------------- scratch (static device globals; no allocation) ----------------
__device__ int   g_degi[NN];
__device__ float g_dinv[NN];
__device__ int   g_bsum[391];
__device__ int   g_bsumex[391];
__device__ int   g_rowptr[NN + 1];
__device__ int   g_cur[NN];
__device__ int   g_csrc[NE];
__device__ float g_ccoef[NE];
__device__ float4 g_hw4[NN * 16];    // h @ W   [N,64] as float4
__device__ float4 g_agg4[NN * 16];   // z buffer (post bias+relu)
__device__ float4 g_h4[NN * 16];     // current activations
__device__ float g_stats[2 * HID];   // per-channel sum, sumsq
__device__ __align__(16) float g_scale[HID];
__device__ __align__(16) float g_shift[HID];
__device__ float g_pool[NB * OUTD];
__device__ float g_cnt[NB];

// ---------------- f32x2 helpers ----------------
__device__ __forceinline__ u64 fma2(u64 a, u64 b, u64 c) {
    u64 d;
    asm("fma.rn.f32x2 %0,%1,%2,%3;" : "=l"(d) : "l"(a), "l"(b), "l"(c));
    return d;
}
__device__ __forceinline__ u64 dup2(float x) {
    u64 d;
    asm("mov.b64 %0,{%1,%1};" : "=l"(d) : "f"(x));
    return d;
}

// ---------------- prep ----------------
__global__ void zero_k() {
    int i = blockIdx.x * 256 + threadIdx.x;
    if (i < NN) g_degi[i] = 0;
    if (i < NB * OUTD) g_pool[i] = 0.f;
    if (i < NB) g_cnt[i] = 0.f;
}

__global__ void count_k(const int* __restrict__ ei, const int* __restrict__ bat) {
    int e = blockIdx.x * 256 + threadIdx.x;
    if (e < NE) atomicAdd(&g_degi[ei[NE + e]], 1);
    if (e < NN) atomicAdd(&g_cnt[bat[e]], 1.f);
}

__global__ void dinv_k() {
    int i = blockIdx.x * 256 + threadIdx.x;
    if (i < NN) g_dinv[i] = rsqrtf((float)g_degi[i] + 1.f);
}

__global__ void scan1_k() {
    __shared__ int sh[256];
    int i = blockIdx.x * 256 + threadIdx.x;
    sh[threadIdx.x] = (i < NN) ? g_degi[i] : 0;
    __syncthreads();
    for (int off = 128; off; off >>= 1) {
        if (threadIdx.x < off) sh[threadIdx.x] += sh[threadIdx.x + off];
        __syncthreads();
    }
    if (threadIdx.x == 0) g_bsum[blockIdx.x] = sh[0];
}

__global__ void scan2_k() {
    __shared__ int sh[512];
    int t = threadIdx.x;
    int v = (t < 391) ? g_bsum[t] : 0;
    sh[t] = v;
    __syncthreads();
    for (int off = 1; off < 512; off <<= 1) {
        int a = (t >= off) ? sh[t - off] : 0;
        __syncthreads();
        sh[t] += a;
        __syncthreads();
    }
    if (t < 391) g_bsumex[t] = sh[t] - v;   // exclusive
    if (t == 0) g_rowptr[NN] = NE;
}

__global__ void scan3_k() {
    __shared__ int sh[256];
    int b = blockIdx.x, t = threadIdx.x;
    int i = b * 256 + t;
    int v = (i < NN) ? g_degi[i] : 0;
    sh[t] = v;
    __syncthreads();
    for (int off = 1; off < 256; off <<= 1) {
        int a = (t >= off) ? sh[t - off] : 0;
        __syncthreads();
        sh[t] += a;
        __syncthreads();
    }
    if (i < NN) {
        int rp = g_bsumex[b] + sh[t] - v;
        g_rowptr[i] = rp;
        g_cur[i] = rp;
    }
}

__global__ void scatter_k(const int* __restrict__ ei) {
    int e = blockIdx.x * 256 + threadIdx.x;
    if (e < NE) {
        int s = ei[e], d = ei[NE + e];
        int pos = atomicAdd(&g_cur[d], 1);
        g_csrc[pos] = s;
        g_ccoef[pos] = g_dinv[s] * g_dinv[d];
    }
}

// ---------------- f32x2 tiled GEMM: Y[nrows,64] = X[nrows,K] @ W[K,64] ----------------
template <int K>
__global__ void __launch_bounds__(256) gemm_64(const float* __restrict__ X,
                                               const float* __restrict__ W,
                                               float* __restrict__ Y, int nrows) {
    __shared__ u64  xs2[64][34];   // x duplicated into both f32x2 lanes; stride 34 keeps 16B align
    __shared__ float ws[32][64];
    const int tid = threadIdx.x;
    if (blockIdx.x == 0 && tid < 128) g_stats[tid] = 0.f;   // zero BN stats for this layer
    const int row0 = blockIdx.x * 64;
    const int tx = tid & 15;
    const int ty = tid >> 4;
    const int c0 = tx * 4;
    const int r0 = ty * 4;
    u64 acc2[4][2] = {};

    for (int kc = 0; kc < K; kc += 32) {
        #pragma unroll
        for (int it = 0; it < 2; ++it) {
            int row = (tid >> 3) + it * 32;     // 0..63
            int kk  = (tid & 7) * 4;            // 0..28
            float4 v = make_float4(0.f, 0.f, 0.f, 0.f);
            int gr = row0 + row;
            if (gr < nrows) v = *(const float4*)(X + (size_t)gr * K + kc + kk);
            xs2[row][kk + 0] = dup2(v.x);
            xs2[row][kk + 1] = dup2(v.y);
            xs2[row][kk + 2] = dup2(v.z);
            xs2[row][kk + 3] = dup2(v.w);
        }
        #pragma unroll
        for (int it = 0; it < 2; ++it) {
            int k  = (tid >> 4) + it * 16;
            int cc = (tid & 15) * 4;
            *(float4*)(&ws[k][cc]) = *(const float4*)(W + (size_t)(kc + k) * 64 + cc);
        }
        __syncthreads();

        #pragma unroll
        for (int k2 = 0; k2 < 16; ++k2) {
            ulonglong2 wa = *(const ulonglong2*)&ws[2 * k2][c0];
            ulonglong2 wb = *(const ulonglong2*)&ws[2 * k2 + 1][c0];
            #pragma unroll
            for (int r = 0; r < 4; ++r) {
                ulonglong2 xk = *(const ulonglong2*)&xs2[r0 + r][2 * k2];
                acc2[r][0] = fma2(xk.x, wa.x, acc2[r][0]);
                acc2[r][1] = fma2(xk.x, wa.y, acc2[r][1]);
                acc2[r][0] = fma2(xk.y, wb.x, acc2[r][0]);
                acc2[r][1] = fma2(xk.y, wb.y, acc2[r][1]);
            }
        }
        __syncthreads();
    }

    #pragma unroll
    for (int r = 0; r < 4; ++r) {
        int gr = row0 + r0 + r;
        if (gr < nrows) {
            float2 a = *(float2*)&acc2[r][0];
            float2 b = *(float2*)&acc2[r][1];
            *(float4*)(Y + (size_t)gr * 64 + c0) = make_float4(a.x, a.y, b.x, b.y);
        }
    }
}

// ---------------- fused CSR aggregation + bias + relu + BN stats ----------------
__global__ void __launch_bounds__(256) csr_agg_k(const float* __restrict__ bias) {
    __shared__ float ss[64], qq[64];
    int t = threadIdx.x;
    if (t < 64) { ss[t] = 0.f; qq[t] = 0.f; }
    __syncthreads();

    int idx = blockIdx.x * 256 + t;            // exactly NN*16
    int node = idx >> 4, q = idx & 15;
    int rs = g_rowptr[node], re = g_rowptr[node + 1];
    float d = g_dinv[node];
    float dd = d * d;
    float4 acc = g_hw4[idx];
    acc.x *= dd; acc.y *= dd; acc.z *= dd; acc.w *= dd;

    for (int j = rs; j < re; ++j) {
        int s = g_csrc[j];
        float c = g_ccoef[j];
        float4 v = g_hw4[s * 16 + q];
        acc.x += c * v.x; acc.y += c * v.y; acc.z += c * v.z; acc.w += c * v.w;
    }
    float4 b4 = ((const float4*)bias)[q];
    acc.x = fmaxf(acc.x + b4.x, 0.f);
    acc.y = fmaxf(acc.y + b4.y, 0.f);
    acc.z = fmaxf(acc.z + b4.z, 0.f);
    acc.w = fmaxf(acc.w + b4.w, 0.f);
    g_agg4[idx] = acc;

    // BN stats: combine lane L with L+16 (same channels, different node), then shared atomics
    float s0 = acc.x, s1 = acc.y, s2 = acc.z, s3 = acc.w;
    float q0 = acc.x * acc.x, q1 = acc.y * acc.y, q2 = acc.z * acc.z, q3 = acc.w * acc.w;
    s0 += __shfl_down_sync(0xffffffffu, s0, 16);
    s1 += __shfl_down_sync(0xffffffffu, s1, 16);
    s2 += __shfl_down_sync(0xffffffffu, s2, 16);
    s3 += __shfl_down_sync(0xffffffffu, s3, 16);
    q0 += __shfl_down_sync(0xffffffffu, q0, 16);
    q1 += __shfl_down_sync(0xffffffffu, q1, 16);
    q2 += __shfl_down_sync(0xffffffffu, q2, 16);
    q3 += __shfl_down_sync(0xffffffffu, q3, 16);
    if ((t & 31) < 16) {
        atomicAdd(&ss[4 * q + 0], s0); atomicAdd(&qq[4 * q + 0], q0);
        atomicAdd(&ss[4 * q + 1], s1); atomicAdd(&qq[4 * q + 1], q1);
        atomicAdd(&ss[4 * q + 2], s2); atomicAdd(&qq[4 * q + 2], q2);
        atomicAdd(&ss[4 * q + 3], s3); atomicAdd(&qq[4 * q + 3], q3);
    }
    __syncthreads();
    if (t < 64) {
        atomicAdd(&g_stats[t], ss[t]);
        atomicAdd(&g_stats[64 + t], qq[t]);
    }
}

__global__ void bn_final_k(const float* __restrict__ gamma, const float* __restrict__ beta) {
    int c = threadIdx.x;
    if (c < HID) {
        float s = g_stats[c], q = g_stats[64 + c];
        float m = s / (float)NN;
        float v = q / (float)NN - m * m;
        float istd = rsqrtf(v + EPSV);
        float sc = istd * gamma[c];
        g_scale[c] = sc;
        g_shift[c] = beta[c] - m * sc;
    }
}

template <bool RES>
__global__ void __launch_bounds__(256) norm_k() {
    int idx = blockIdx.x * 256 + threadIdx.x;          // over NN*16
    int c4 = idx & 15;
    float4 sc = ((const float4*)g_scale)[c4];
    float4 sh = ((const float4*)g_shift)[c4];
    float4 z = g_agg4[idx];
    float4 h;
    h.x = z.x * sc.x + sh.x;
    h.y = z.y * sc.y + sh.y;
    h.z = z.z * sc.z + sh.z;
    h.w = z.w * sc.w + sh.w;
    if (RES) {
        float4 o = g_h4[idx];
        h.x += o.x; h.y += o.y; h.z += o.z; h.w += o.w;
    }
    g_h4[idx] = h;
}

// ---------------- output layer (64 -> 2) ----------------
__global__ void __launch_bounds__(256) gemm_out_k(const float* __restrict__ X,
                                                  const float* __restrict__ W,
                                                  float* __restrict__ Y) {
    __shared__ float w0[64], w1[64];
    if (threadIdx.x < 64) {
        w0[threadIdx.x] = W[threadIdx.x * 2];
        w1[threadIdx.x] = W[threadIdx.x * 2 + 1];
    }
    __syncthreads();
    int warp = threadIdx.x >> 5, lane = threadIdx.x & 31;
    int row = blockIdx.x * 8 + warp;
    if (row >= NN) return;
    const float* xr = X + (size_t)row * 64;
    float x0 = xr[lane], x1 = xr[lane + 32];
    float a0 = x0 * w0[lane] + x1 * w0[lane + 32];
    float a1 = x0 * w1[lane] + x1 * w1[lane + 32];
    #pragma unroll
    for (int o = 16; o > 0; o >>= 1) {
        a0 += __shfl_down_sync(0xffffffffu, a0, o);
        a1 += __shfl_down_sync(0xffffffffu, a1, o);
    }
    if (lane == 0) {
        Y[row * 2]     = a0;
        Y[row * 2 + 1] = a1;
    }
}

// fused: CSR aggregation (2 channels) + segment pooling
__global__ void __launch_bounds__(256) csr2_pool_k(const int* __restrict__ bat) {
    __shared__ float sp[NB * OUTD];
    int t = threadIdx.x;
    if (t < NB * OUTD) sp[t] = 0.f;
    __syncthreads();
    int i = blockIdx.x * 256 + t;
    if (i < NN) {
        const float2* H = (const float2*)g_hw4;
        float d = g_dinv[i];
        float dd = d * d;
        float2 a = H[i];
        a.x *= dd; a.y *= dd;
        int re = g_rowptr[i + 1];
        for (int j = g_rowptr[i]; j < re; ++j) {
            int s = g_csrc[j];
            float c = g_ccoef[j];
            float2 v = H[s];
            a.x += c * v.x; a.y += c * v.y;
        }
        int b = bat[i];
        atomicAdd(&sp[2 * b],     a.x);
        atomicAdd(&sp[2 * b + 1], a.y);
    }
    __syncthreads();
    if (t < NB * OUTD) atomicAdd(&g_pool[t], sp[t]);
}

__global__ void final_k(const float* __restrict__ b_out, float* __restrict__ out) {
    int t = threadIdx.x;
    if (t < NB * OUTD) {
        int b = t >> 1, c = t & 1;
        out[t] = g_pool[t] / fmaxf(g_cnt[b], 1.f) + b_out[c];
    }
}

// ---------------- driver ----------------
extern "C" void kernel_launch(void* const* d_in, const int* in_sizes, int n_in,
                              void* d_out, int out_size) {
    const float* x       = (const float*)d_in[0];
    const float* W_in    = (const float*)d_in[1];
    const float* b_in    = (const float*)d_in[2];
    const float* W_h     = (const float*)d_in[3];
    const float* b_h     = (const float*)d_in[4];
    const float* W_out   = (const float*)d_in[5];
    const float* b_out   = (const float*)d_in[6];
    const float* bn_g    = (const float*)d_in[7];
    const float* bn_b    = (const float*)d_in[8];
    const int*   ei      = (const int*)d_in[9];      // int32: JAX x64 disabled
    const int*   bat     = (const int*)d_in[10];     // int32

    float* out = (float*)d_out;

    void *p_hw, *p_h;
    cudaGetSymbolAddress(&p_hw, g_hw4);
    cudaGetSymbolAddress(&p_h, g_h4);
    float* hw = (float*)p_hw;
    float* h  = (float*)p_h;

    // prep: degrees, dinv, CSR (reused by all 4 layers), batch counts
    zero_k<<<391, 256>>>();
    count_k<<<4688, 256>>>(ei, bat);
    dinv_k<<<391, 256>>>();
    scan1_k<<<391, 256>>>();
    scan2_k<<<1, 512>>>();
    scan3_k<<<391, 256>>>();
    scatter_k<<<4688, 256>>>(ei);

    // layer 1: 128 -> 64
    gemm_64<IND><<<1563, 256>>>(x, W_in, hw, NN);
    csr_agg_k<<<6250, 256>>>(b_in);
    bn_final_k<<<1, 64>>>(bn_g, bn_b);
    norm_k<false><<<6250, 256>>>();

    // hidden layers: 64 -> 64 with residual
    for (int i = 0; i < 2; ++i) {
        gemm_64<HID><<<1563, 256>>>(h, W_h + i * HID * HID, hw, NN);
        csr_agg_k<<<6250, 256>>>(b_h + i * HID);
        bn_final_k<<<1, 64>>>(bn_g + (i + 1) * HID, bn_b + (i + 1) * HID);
        norm_k<true><<<6250, 256>>>();
    }

    // output layer: 64 -> 2, then global mean pool
    gemm_out_k<<<12500, 256>>>(h, W_out, hw);
    csr2_pool_k<<<391, 256>>>(bat);
    final_k<<<1, 128>>>(b_out, out);
}

// round 4
// speedup vs baseline: 1.2789x; 1.0796x over previous
#include <cuda_runtime.h>

#define NN   100000
#define NE   1200000
#define NB   64
#define HID  64
#define IND  128
#define OUTD 2
#define EPSV 1e-5f

typedef unsigned long long u64;

// ---------------- scratch (static device globals; no allocation) ----------------
__device__ int   g_degi[NN];
__device__ float g_dinv[NN];
__device__ int   g_bsum[391];
__device__ int   g_bsumex[391];
__device__ int   g_rowptr[NN + 1];
__device__ int   g_cur[NN];
__device__ float2 g_edge[NE];        // {coef, src-as-float-bits} packed
__device__ float4 g_hw4[NN * 16];    // h @ W   [N,64] as float4
__device__ float4 g_agg4[NN * 16];   // z buffer (post bias+relu)
__device__ float4 g_h4[NN * 16];     // current activations (residual source)
__device__ float g_stats[2 * HID];   // per-channel sum, sumsq
__device__ __align__(16) float g_scale[HID];
__device__ __align__(16) float g_shift[HID];
__device__ float g_pool[NB * OUTD];
__device__ float g_cnt[NB];

// ---------------- f32x2 helpers ----------------
__device__ __forceinline__ u64 fma2(u64 a, u64 b, u64 c) {
    u64 d;
    asm("fma.rn.f32x2 %0,%1,%2,%3;" : "=l"(d) : "l"(a), "l"(b), "l"(c));
    return d;
}
__device__ __forceinline__ u64 dup2(float x) {
    u64 d;
    asm("mov.b64 %0,{%1,%1};" : "=l"(d) : "f"(x));
    return d;
}

// ---------------- prep ----------------
__global__ void zero_k() {
    int i = blockIdx.x * 256 + threadIdx.x;
    if (i < NN) g_degi[i] = 0;
    if (i < NB * OUTD) g_pool[i] = 0.f;
    if (i < NB) g_cnt[i] = 0.f;
}

__global__ void count_k(const int* __restrict__ ei, const int* __restrict__ bat) {
    int e = blockIdx.x * 256 + threadIdx.x;
    if (e < NE) atomicAdd(&g_degi[ei[NE + e]], 1);
    if (e < NN) atomicAdd(&g_cnt[bat[e]], 1.f);
}

// block sums for scan + dinv (merged)
__global__ void scan1_k() {
    __shared__ int sh[256];
    int i = blockIdx.x * 256 + threadIdx.x;
    int d = (i < NN) ? g_degi[i] : 0;
    if (i < NN) g_dinv[i] = rsqrtf((float)d + 1.f);
    sh[threadIdx.x] = d;
    __syncthreads();
    for (int off = 128; off; off >>= 1) {
        if (threadIdx.x < off) sh[threadIdx.x] += sh[threadIdx.x + off];
        __syncthreads();
    }
    if (threadIdx.x == 0) g_bsum[blockIdx.x] = sh[0];
}

__global__ void scan2_k() {
    __shared__ int sh[512];
    int t = threadIdx.x;
    int v = (t < 391) ? g_bsum[t] : 0;
    sh[t] = v;
    __syncthreads();
    for (int off = 1; off < 512; off <<= 1) {
        int a = (t >= off) ? sh[t - off] : 0;
        __syncthreads();
        sh[t] += a;
        __syncthreads();
    }
    if (t < 391) g_bsumex[t] = sh[t] - v;   // exclusive
    if (t == 0) g_rowptr[NN] = NE;
}

__global__ void scan3_k() {
    __shared__ int sh[256];
    int b = blockIdx.x, t = threadIdx.x;
    int i = b * 256 + t;
    int v = (i < NN) ? g_degi[i] : 0;
    sh[t] = v;
    __syncthreads();
    for (int off = 1; off < 256; off <<= 1) {
        int a = (t >= off) ? sh[t - off] : 0;
        __syncthreads();
        sh[t] += a;
        __syncthreads();
    }
    if (i < NN) {
        int rp = g_bsumex[b] + sh[t] - v;
        g_rowptr[i] = rp;
        g_cur[i] = rp;
    }
}

__global__ void scatter_k(const int* __restrict__ ei) {
    int e = blockIdx.x * 256 + threadIdx.x;
    if (e < NE) {
        int s = ei[e], d = ei[NE + e];
        int pos = atomicAdd(&g_cur[d], 1);
        g_edge[pos] = make_float2(g_dinv[s] * g_dinv[d], __int_as_float(s));
    }
}

// ---------------- f32x2 tiled GEMM: Y[nrows,64] = Xform(X)[nrows,K] @ W[K,64] ----
// MODE 0: plain (X used as-is)
// MODE 1: h = X*scale+shift          (fused BN of previous layer), h stored to g_h4
// MODE 2: h = X*scale+shift + g_h4   (fused BN + residual),        h stored to g_h4
template <int K, int MODE>
__global__ void __launch_bounds__(256) gemm_64(const float* __restrict__ X,
                                               const float* __restrict__ W,
                                               float* __restrict__ Y, int nrows) {
    __shared__ u64  xs2[64][34];   // x duplicated into both f32x2 lanes
    __shared__ float ws[32][64];
    const int tid = threadIdx.x;
    if (blockIdx.x == 0 && tid < 128) g_stats[tid] = 0.f;   // zero BN stats for this layer
    const int row0 = blockIdx.x * 64;
    const int tx = tid & 15;
    const int ty = tid >> 4;
    const int c0 = tx * 4;
    const int r0 = ty * 4;
    float* hh = (float*)g_h4;
    u64 acc2[4][2] = {};

    for (int kc = 0; kc < K; kc += 32) {
        #pragma unroll
        for (int it = 0; it < 2; ++it) {
            int row = (tid >> 3) + it * 32;     // 0..63
            int kk  = (tid & 7) * 4;            // 0..28
            float4 v = make_float4(0.f, 0.f, 0.f, 0.f);
            int gr = row0 + row;
            if (gr < nrows) {
                v = *(const float4*)(X + (size_t)gr * K + kc + kk);
                if (MODE > 0) {
                    float4 sc = *(const float4*)(g_scale + kc + kk);
                    float4 sh = *(const float4*)(g_shift + kc + kk);
                    v.x = v.x * sc.x + sh.x;
                    v.y = v.y * sc.y + sh.y;
                    v.z = v.z * sc.z + sh.z;
                    v.w = v.w * sc.w + sh.w;
                    if (MODE == 2) {
                        float4 o = *(const float4*)(hh + (size_t)gr * 64 + kc + kk);
                        v.x += o.x; v.y += o.y; v.z += o.z; v.w += o.w;
                    }
                    *(float4*)(hh + (size_t)gr * 64 + kc + kk) = v;
                }
            }
            xs2[row][kk + 0] = dup2(v.x);
            xs2[row][kk + 1] = dup2(v.y);
            xs2[row][kk + 2] = dup2(v.z);
            xs2[row][kk + 3] = dup2(v.w);
        }
        #pragma unroll
        for (int it = 0; it < 2; ++it) {
            int k  = (tid >> 4) + it * 16;
            int cc = (tid & 15) * 4;
            *(float4*)(&ws[k][cc]) = *(const float4*)(W + (size_t)(kc + k) * 64 + cc);
        }
        __syncthreads();

        #pragma unroll
        for (int k2 = 0; k2 < 16; ++k2) {
            ulonglong2 wa = *(const ulonglong2*)&ws[2 * k2][c0];
            ulonglong2 wb = *(const ulonglong2*)&ws[2 * k2 + 1][c0];
            #pragma unroll
            for (int r = 0; r < 4; ++r) {
                ulonglong2 xk = *(const ulonglong2*)&xs2[r0 + r][2 * k2];
                acc2[r][0] = fma2(xk.x, wa.x, acc2[r][0]);
                acc2[r][1] = fma2(xk.x, wa.y, acc2[r][1]);
                acc2[r][0] = fma2(xk.y, wb.x, acc2[r][0]);
                acc2[r][1] = fma2(xk.y, wb.y, acc2[r][1]);
            }
        }
        __syncthreads();
    }

    #pragma unroll
    for (int r = 0; r < 4; ++r) {
        int gr = row0 + r0 + r;
        if (gr < nrows) {
            float2 a = *(float2*)&acc2[r][0];
            float2 b = *(float2*)&acc2[r][1];
            *(float4*)(Y + (size_t)gr * 64 + c0) = make_float4(a.x, a.y, b.x, b.y);
        }
    }
}

// ---------------- fused CSR aggregation + bias + relu + BN stats ----------------
__global__ void __launch_bounds__(256) csr_agg_k(const float* __restrict__ bias) {
    __shared__ float ss[64], qq[64];
    int t = threadIdx.x;
    if (t < 64) { ss[t] = 0.f; qq[t] = 0.f; }
    __syncthreads();

    int idx = blockIdx.x * 256 + t;            // exactly NN*16
    int node = idx >> 4, q = idx & 15;
    int rs = g_rowptr[node], re = g_rowptr[node + 1];
    float d = g_dinv[node];
    float dd = d * d;
    float4 acc = g_hw4[idx];
    acc.x *= dd; acc.y *= dd; acc.z *= dd; acc.w *= dd;

    int j = rs;
    for (; j + 4 <= re; j += 4) {              // 4-way MLP
        float2 e0 = g_edge[j], e1 = g_edge[j + 1], e2 = g_edge[j + 2], e3 = g_edge[j + 3];
        float4 v0 = g_hw4[__float_as_int(e0.y) * 16 + q];
        float4 v1 = g_hw4[__float_as_int(e1.y) * 16 + q];
        float4 v2 = g_hw4[__float_as_int(e2.y) * 16 + q];
        float4 v3 = g_hw4[__float_as_int(e3.y) * 16 + q];
        acc.x += e0.x * v0.x + e1.x * v1.x + e2.x * v2.x + e3.x * v3.x;
        acc.y += e0.x * v0.y + e1.x * v1.y + e2.x * v2.y + e3.x * v3.y;
        acc.z += e0.x * v0.z + e1.x * v1.z + e2.x * v2.z + e3.x * v3.z;
        acc.w += e0.x * v0.w + e1.x * v1.w + e2.x * v2.w + e3.x * v3.w;
    }
    for (; j < re; ++j) {
        float2 e = g_edge[j];
        float4 v = g_hw4[__float_as_int(e.y) * 16 + q];
        acc.x += e.x * v.x; acc.y += e.x * v.y; acc.z += e.x * v.z; acc.w += e.x * v.w;
    }

    float4 b4 = ((const float4*)bias)[q];
    acc.x = fmaxf(acc.x + b4.x, 0.f);
    acc.y = fmaxf(acc.y + b4.y, 0.f);
    acc.z = fmaxf(acc.z + b4.z, 0.f);
    acc.w = fmaxf(acc.w + b4.w, 0.f);
    g_agg4[idx] = acc;

    // BN stats: combine lane L with L+16 (same channels), then shared atomics
    float s0 = acc.x, s1 = acc.y, s2 = acc.z, s3 = acc.w;
    float q0 = acc.x * acc.x, q1 = acc.y * acc.y, q2 = acc.z * acc.z, q3 = acc.w * acc.w;
    s0 += __shfl_down_sync(0xffffffffu, s0, 16);
    s1 += __shfl_down_sync(0xffffffffu, s1, 16);
    s2 += __shfl_down_sync(0xffffffffu, s2, 16);
    s3 += __shfl_down_sync(0xffffffffu, s3, 16);
    q0 += __shfl_down_sync(0xffffffffu, q0, 16);
    q1 += __shfl_down_sync(0xffffffffu, q1, 16);
    q2 += __shfl_down_sync(0xffffffffu, q2, 16);
    q3 += __shfl_down_sync(0xffffffffu, q3, 16);
    if ((t & 31) < 16) {
        atomicAdd(&ss[4 * q + 0], s0); atomicAdd(&qq[4 * q + 0], q0);
        atomicAdd(&ss[4 * q + 1], s1); atomicAdd(&qq[4 * q + 1], q1);
        atomicAdd(&ss[4 * q + 2], s2); atomicAdd(&qq[4 * q + 2], q2);
        atomicAdd(&ss[4 * q + 3], s3); atomicAdd(&qq[4 * q + 3], q3);
    }
    __syncthreads();
    if (t < 64) {
        atomicAdd(&g_stats[t], ss[t]);
        atomicAdd(&g_stats[64 + t], qq[t]);
    }
}

__global__ void bn_final_k(const float* __restrict__ gamma, const float* __restrict__ beta) {
    int c = threadIdx.x;
    if (c < HID) {
        float s = g_stats[c], q = g_stats[64 + c];
        float m = s / (float)NN;
        float v = q / (float)NN - m * m;
        float istd = rsqrtf(v + EPSV);
        float sc = istd * gamma[c];
        g_scale[c] = sc;
        g_shift[c] = beta[c] - m * sc;
    }
}

// ---------------- output layer: fused BN+residual transform, 64 -> 2 ----------------
__global__ void __launch_bounds__(256) gemm_out_k(const float* __restrict__ Z,
                                                  const float* __restrict__ W,
                                                  float* __restrict__ Y) {
    __shared__ float w0[64], w1[64], ssc[64], ssh[64];
    if (threadIdx.x < 64) {
        w0[threadIdx.x] = W[threadIdx.x * 2];
        w1[threadIdx.x] = W[threadIdx.x * 2 + 1];
        ssc[threadIdx.x] = g_scale[threadIdx.x];
        ssh[threadIdx.x] = g_shift[threadIdx.x];
    }
    __syncthreads();
    int warp = threadIdx.x >> 5, lane = threadIdx.x & 31;
    int row = blockIdx.x * 8 + warp;
    if (row >= NN) return;
    const float* zr = Z + (size_t)row * 64;
    const float* hr = (const float*)g_h4 + (size_t)row * 64;
    float h0 = zr[lane]      * ssc[lane]      + ssh[lane]      + hr[lane];
    float h1 = zr[lane + 32] * ssc[lane + 32] + ssh[lane + 32] + hr[lane + 32];
    float a0 = h0 * w0[lane] + h1 * w0[lane + 32];
    float a1 = h0 * w1[lane] + h1 * w1[lane + 32];
    #pragma unroll
    for (int o = 16; o > 0; o >>= 1) {
        a0 += __shfl_down_sync(0xffffffffu, a0, o);
        a1 += __shfl_down_sync(0xffffffffu, a1, o);
    }
    if (lane == 0) {
        Y[row * 2]     = a0;
        Y[row * 2 + 1] = a1;
    }
}

// fused: CSR aggregation (2 channels) + segment pooling
__global__ void __launch_bounds__(256) csr2_pool_k(const int* __restrict__ bat) {
    __shared__ float sp[NB * OUTD];
    int t = threadIdx.x;
    if (t < NB * OUTD) sp[t] = 0.f;
    __syncthreads();
    int i = blockIdx.x * 256 + t;
    if (i < NN) {
        const float2* H = (const float2*)g_hw4;
        float d = g_dinv[i];
        float dd = d * d;
        float2 a = H[i];
        a.x *= dd; a.y *= dd;
        int rs = g_rowptr[i], re = g_rowptr[i + 1];
        int j = rs;
        for (; j + 4 <= re; j += 4) {
            float2 e0 = g_edge[j], e1 = g_edge[j + 1], e2 = g_edge[j + 2], e3 = g_edge[j + 3];
            float2 v0 = H[__float_as_int(e0.y)];
            float2 v1 = H[__float_as_int(e1.y)];
            float2 v2 = H[__float_as_int(e2.y)];
            float2 v3 = H[__float_as_int(e3.y)];
            a.x += e0.x * v0.x + e1.x * v1.x + e2.x * v2.x + e3.x * v3.x;
            a.y += e0.x * v0.y + e1.x * v1.y + e2.x * v2.y + e3.x * v3.y;
        }
        for (; j < re; ++j) {
            float2 e = g_edge[j];
            float2 v = H[__float_as_int(e.y)];
            a.x += e.x * v.x; a.y += e.x * v.y;
        }
        int b = bat[i];
        atomicAdd(&sp[2 * b],     a.x);
        atomicAdd(&sp[2 * b + 1], a.y);
    }
    __syncthreads();
    if (t < NB * OUTD) atomicAdd(&g_pool[t], sp[t]);
}

__global__ void final_k(const float* __restrict__ b_out, float* __restrict__ out) {
    int t = threadIdx.x;
    if (t < NB * OUTD) {
        int b = t >> 1, c = t & 1;
        out[t] = g_pool[t] / fmaxf(g_cnt[b], 1.f) + b_out[c];
    }
}

// ---------------- driver ----------------
extern "C" void kernel_launch(void* const* d_in, const int* in_sizes, int n_in,
                              void* d_out, int out_size) {
    const float* x       = (const float*)d_in[0];
    const float* W_in    = (const float*)d_in[1];
    const float* b_in    = (const float*)d_in[2];
    const float* W_h     = (const float*)d_in[3];
    const float* b_h     = (const float*)d_in[4];
    const float* W_out   = (const float*)d_in[5];
    const float* b_out   = (const float*)d_in[6];
    const float* bn_g    = (const float*)d_in[7];
    const float* bn_b    = (const float*)d_in[8];
    const int*   ei      = (const int*)d_in[9];      // int32: JAX x64 disabled
    const int*   bat     = (const int*)d_in[10];     // int32

    float* out = (float*)d_out;

    void *p_hw, *p_z;
    cudaGetSymbolAddress(&p_hw, g_hw4);
    cudaGetSymbolAddress(&p_z, g_agg4);
    float* hw = (float*)p_hw;
    float* z  = (float*)p_z;

    // prep: degrees, dinv, CSR (reused by all 4 layers), batch counts
    zero_k<<<391, 256>>>();
    count_k<<<4688, 256>>>(ei, bat);
    scan1_k<<<391, 256>>>();
    scan2_k<<<1, 512>>>();
    scan3_k<<<391, 256>>>();
    scatter_k<<<4688, 256>>>(ei);

    // layer 1: 128 -> 64 (plain input)
    gemm_64<IND, 0><<<1563, 256>>>(x, W_in, hw, NN);
    csr_agg_k<<<6250, 256>>>(b_in);
    bn_final_k<<<1, 64>>>(bn_g, bn_b);

    // layer 2: consumes z1 with fused BN (no residual for h1)
    gemm_64<HID, 1><<<1563, 256>>>(z, W_h, hw, NN);
    csr_agg_k<<<6250, 256>>>(b_h);
    bn_final_k<<<1, 64>>>(bn_g + HID, bn_b + HID);

    // layer 3: consumes z2 with fused BN + residual (h2 = z2*sc+sh + h1)
    gemm_64<HID, 2><<<1563, 256>>>(z, W_h + HID * HID, hw, NN);
    csr_agg_k<<<6250, 256>>>(b_h + HID);
    bn_final_k<<<1, 64>>>(bn_g + 2 * HID, bn_b + 2 * HID);

    // output layer: fused BN + residual transform inside gemm_out, then pool
    gemm_out_k<<<12500, 256>>>(z, W_out, hw);
    csr2_pool_k<<<391, 256>>>(bat);
    final_k<<<1, 128>>>(b_out, out);
}

// round 5
// speedup vs baseline: 1.3610x; 1.0642x over previous
#include <cuda_runtime.h>
#include <cuda_fp16.h>

#define NN   100000
#define NE   1200000
#define NB   64
#define HID  64
#define IND  128
#define OUTD 2
#define EPSV 1e-5f

typedef unsigned long long u64;

// ---------------- scratch (static device globals; no allocation) ----------------
__device__ int   g_degi[NN];
__device__ float g_dinv[NN];
__device__ int   g_bsum[391];
__device__ int   g_bsumex[391];
__device__ int   g_rowptr[NN + 1];
__device__ int   g_cur[NN];
__device__ float2 g_edge[NE];          // {coef, src-as-float-bits}
__device__ uint2  g_hwh[NN * 16];      // h @ W as fp16x4 per uint2 (64 ch/node = 16 uint2)
__device__ float2 g_hw2[NN];           // output-layer hW [N,2] fp32
__device__ float4 g_agg4[NN * 16];     // z buffer (post bias+relu), fp32
__device__ float4 g_h4[NN * 16];       // residual activations, fp32
__device__ float g_stats[3][2 * HID];  // per-layer {sum, sumsq}
__device__ float g_pool[NB * OUTD];
__device__ float g_cnt[NB];

// ---------------- f32x2 helpers ----------------
__device__ __forceinline__ u64 fma2(u64 a, u64 b, u64 c) {
    u64 d;
    asm("fma.rn.f32x2 %0,%1,%2,%3;" : "=l"(d) : "l"(a), "l"(b), "l"(c));
    return d;
}
__device__ __forceinline__ u64 dup2(float x) {
    u64 d;
    asm("mov.b64 %0,{%1,%1};" : "=l"(d) : "f"(x));
    return d;
}

// ---------------- prep ----------------
__global__ void zero_k() {
    int i = blockIdx.x * 256 + threadIdx.x;
    if (i < NN) g_degi[i] = 0;
    if (i < 3 * 2 * HID) ((float*)g_stats)[i] = 0.f;
    if (i < NB * OUTD) g_pool[i] = 0.f;
    if (i < NB) g_cnt[i] = 0.f;
}

__global__ void count_k(const int* __restrict__ ei, const int* __restrict__ bat) {
    int e = blockIdx.x * 256 + threadIdx.x;
    if (e < NE) atomicAdd(&g_degi[ei[NE + e]], 1);
    if (e < NN) atomicAdd(&g_cnt[bat[e]], 1.f);
}

__global__ void scan1_k() {
    __shared__ int sh[256];
    int i = blockIdx.x * 256 + threadIdx.x;
    int d = (i < NN) ? g_degi[i] : 0;
    if (i < NN) g_dinv[i] = rsqrtf((float)d + 1.f);
    sh[threadIdx.x] = d;
    __syncthreads();
    for (int off = 128; off; off >>= 1) {
        if (threadIdx.x < off) sh[threadIdx.x] += sh[threadIdx.x + off];
        __syncthreads();
    }
    if (threadIdx.x == 0) g_bsum[blockIdx.x] = sh[0];
}

__global__ void scan2_k() {
    __shared__ int sh[512];
    int t = threadIdx.x;
    int v = (t < 391) ? g_bsum[t] : 0;
    sh[t] = v;
    __syncthreads();
    for (int off = 1; off < 512; off <<= 1) {
        int a = (t >= off) ? sh[t - off] : 0;
        __syncthreads();
        sh[t] += a;
        __syncthreads();
    }
    if (t < 391) g_bsumex[t] = sh[t] - v;
    if (t == 0) g_rowptr[NN] = NE;
}

__global__ void scan3_k() {
    __shared__ int sh[256];
    int b = blockIdx.x, t = threadIdx.x;
    int i = b * 256 + t;
    int v = (i < NN) ? g_degi[i] : 0;
    sh[t] = v;
    __syncthreads();
    for (int off = 1; off < 256; off <<= 1) {
        int a = (t >= off) ? sh[t - off] : 0;
        __syncthreads();
        sh[t] += a;
        __syncthreads();
    }
    if (i < NN) {
        int rp = g_bsumex[b] + sh[t] - v;
        g_rowptr[i] = rp;
        g_cur[i] = rp;
    }
}

__global__ void scatter_k(const int* __restrict__ ei) {
    int e = blockIdx.x * 256 + threadIdx.x;
    if (e < NE) {
        int s = ei[e], d = ei[NE + e];
        int pos = atomicAdd(&g_cur[d], 1);
        g_edge[pos] = make_float2(g_dinv[s] * g_dinv[d], __int_as_float(s));
    }
}

// ---------------- f32x2 tiled GEMM: hwh[nrows,64](fp16) = Xform(X)[nrows,K] @ W[K,64] ----
// MODE 0: plain (X used as-is)
// MODE 1: h = X*scale+shift          (BN from stats), h -> g_h4
// MODE 2: h = X*scale+shift + g_h4   (BN + residual), h -> g_h4
template <int K, int MODE>
__global__ void __launch_bounds__(256) gemm_64(const float* __restrict__ X,
                                               const float* __restrict__ W,
                                               const float* __restrict__ gamma,
                                               const float* __restrict__ beta,
                                               const float* __restrict__ st,
                                               int nrows) {
    __shared__ u64  xs2[64][34];
    __shared__ float ws[32][64];
    __shared__ float ssc[64], ssh[64];
    const int tid = threadIdx.x;
    if (MODE > 0) {
        if (tid < 64) {
            float s = st[tid], q = st[64 + tid];
            float m = s * (1.f / NN);
            float v = q * (1.f / NN) - m * m;
            float istd = rsqrtf(v + EPSV);
            float sc = istd * gamma[tid];
            ssc[tid] = sc;
            ssh[tid] = beta[tid] - m * sc;
        }
        __syncthreads();
    }
    const int row0 = blockIdx.x * 64;
    const int tx = tid & 15;
    const int ty = tid >> 4;
    const int c0 = tx * 4;
    const int r0 = ty * 4;
    float* hh = (float*)g_h4;
    u64 acc2[4][2] = {};

    for (int kc = 0; kc < K; kc += 32) {
        #pragma unroll
        for (int it = 0; it < 2; ++it) {
            int row = (tid >> 3) + it * 32;
            int kk  = (tid & 7) * 4;
            float4 v = make_float4(0.f, 0.f, 0.f, 0.f);
            int gr = row0 + row;
            if (gr < nrows) {
                v = *(const float4*)(X + (size_t)gr * K + kc + kk);
                if (MODE > 0) {
                    v.x = v.x * ssc[kc + kk + 0] + ssh[kc + kk + 0];
                    v.y = v.y * ssc[kc + kk + 1] + ssh[kc + kk + 1];
                    v.z = v.z * ssc[kc + kk + 2] + ssh[kc + kk + 2];
                    v.w = v.w * ssc[kc + kk + 3] + ssh[kc + kk + 3];
                    if (MODE == 2) {
                        float4 o = *(const float4*)(hh + (size_t)gr * 64 + kc + kk);
                        v.x += o.x; v.y += o.y; v.z += o.z; v.w += o.w;
                    }
                    *(float4*)(hh + (size_t)gr * 64 + kc + kk) = v;
                }
            }
            xs2[row][kk + 0] = dup2(v.x);
            xs2[row][kk + 1] = dup2(v.y);
            xs2[row][kk + 2] = dup2(v.z);
            xs2[row][kk + 3] = dup2(v.w);
        }
        #pragma unroll
        for (int it = 0; it < 2; ++it) {
            int k  = (tid >> 4) + it * 16;
            int cc = (tid & 15) * 4;
            *(float4*)(&ws[k][cc]) = *(const float4*)(W + (size_t)(kc + k) * 64 + cc);
        }
        __syncthreads();

        #pragma unroll
        for (int k2 = 0; k2 < 16; ++k2) {
            ulonglong2 wa = *(const ulonglong2*)&ws[2 * k2][c0];
            ulonglong2 wb = *(const ulonglong2*)&ws[2 * k2 + 1][c0];
            #pragma unroll
            for (int r = 0; r < 4; ++r) {
                ulonglong2 xk = *(const ulonglong2*)&xs2[r0 + r][2 * k2];
                acc2[r][0] = fma2(xk.x, wa.x, acc2[r][0]);
                acc2[r][1] = fma2(xk.x, wa.y, acc2[r][1]);
                acc2[r][0] = fma2(xk.y, wb.x, acc2[r][0]);
                acc2[r][1] = fma2(xk.y, wb.y, acc2[r][1]);
            }
        }
        __syncthreads();
    }

    #pragma unroll
    for (int r = 0; r < 4; ++r) {
        int gr = row0 + r0 + r;
        if (gr < nrows) {
            float2 a = *(float2*)&acc2[r][0];
            float2 b = *(float2*)&acc2[r][1];
            __half2 p0 = __floats2half2_rn(a.x, a.y);
            __half2 p1 = __floats2half2_rn(b.x, b.y);
            uint2 pk;
            pk.x = *(unsigned int*)&p0;
            pk.y = *(unsigned int*)&p1;
            g_hwh[gr * 16 + tx] = pk;
        }
    }
}

// ---------------- fused CSR aggregation + bias + relu + BN stats ----------------
__device__ __forceinline__ float4 h4tof4(uint2 raw) {
    __half2 a = *(__half2*)&raw.x;
    __half2 b = *(__half2*)&raw.y;
    float2 f0 = __half22float2(a);
    float2 f1 = __half22float2(b);
    return make_float4(f0.x, f0.y, f1.x, f1.y);
}

__global__ void __launch_bounds__(256) csr_agg_k(const float* __restrict__ bias,
                                                 float* __restrict__ stats) {
    __shared__ float ss[64], qq[64];
    int t = threadIdx.x;
    if (t < 64) { ss[t] = 0.f; qq[t] = 0.f; }
    __syncthreads();

    int idx = blockIdx.x * 256 + t;            // exactly NN*16
    int node = idx >> 4, q = idx & 15;
    int rs = g_rowptr[node], re = g_rowptr[node + 1];
    float d = g_dinv[node];
    float dd = d * d;
    float4 acc = h4tof4(g_hwh[idx]);
    acc.x *= dd; acc.y *= dd; acc.z *= dd; acc.w *= dd;

    int j = rs;
    for (; j + 4 <= re; j += 4) {              // 4-way MLP
        float2 e0 = g_edge[j], e1 = g_edge[j + 1], e2 = g_edge[j + 2], e3 = g_edge[j + 3];
        float4 v0 = h4tof4(g_hwh[__float_as_int(e0.y) * 16 + q]);
        float4 v1 = h4tof4(g_hwh[__float_as_int(e1.y) * 16 + q]);
        float4 v2 = h4tof4(g_hwh[__float_as_int(e2.y) * 16 + q]);
        float4 v3 = h4tof4(g_hwh[__float_as_int(e3.y) * 16 + q]);
        acc.x += e0.x * v0.x + e1.x * v1.x + e2.x * v2.x + e3.x * v3.x;
        acc.y += e0.x * v0.y + e1.x * v1.y + e2.x * v2.y + e3.x * v3.y;
        acc.z += e0.x * v0.z + e1.x * v1.z + e2.x * v2.z + e3.x * v3.z;
        acc.w += e0.x * v0.w + e1.x * v1.w + e2.x * v2.w + e3.x * v3.w;
    }
    for (; j < re; ++j) {
        float2 e = g_edge[j];
        float4 v = h4tof4(g_hwh[__float_as_int(e.y) * 16 + q]);
        acc.x += e.x * v.x; acc.y += e.x * v.y; acc.z += e.x * v.z; acc.w += e.x * v.w;
    }

    float4 b4 = ((const float4*)bias)[q];
    acc.x = fmaxf(acc.x + b4.x, 0.f);
    acc.y = fmaxf(acc.y + b4.y, 0.f);
    acc.z = fmaxf(acc.z + b4.z, 0.f);
    acc.w = fmaxf(acc.w + b4.w, 0.f);
    g_agg4[idx] = acc;

    float s0 = acc.x, s1 = acc.y, s2 = acc.z, s3 = acc.w;
    float q0 = acc.x * acc.x, q1 = acc.y * acc.y, q2 = acc.z * acc.z, q3 = acc.w * acc.w;
    s0 += __shfl_down_sync(0xffffffffu, s0, 16);
    s1 += __shfl_down_sync(0xffffffffu, s1, 16);
    s2 += __shfl_down_sync(0xffffffffu, s2, 16);
    s3 += __shfl_down_sync(0xffffffffu, s3, 16);
    q0 += __shfl_down_sync(0xffffffffu, q0, 16);
    q1 += __shfl_down_sync(0xffffffffu, q1, 16);
    q2 += __shfl_down_sync(0xffffffffu, q2, 16);
    q3 += __shfl_down_sync(0xffffffffu, q3, 16);
    if ((t & 31) < 16) {
        atomicAdd(&ss[4 * q + 0], s0); atomicAdd(&qq[4 * q + 0], q0);
        atomicAdd(&ss[4 * q + 1], s1); atomicAdd(&qq[4 * q + 1], q1);
        atomicAdd(&ss[4 * q + 2], s2); atomicAdd(&qq[4 * q + 2], q2);
        atomicAdd(&ss[4 * q + 3], s3); atomicAdd(&qq[4 * q + 3], q3);
    }
    __syncthreads();
    if (t < 64) {
        atomicAdd(&stats[t], ss[t]);
        atomicAdd(&stats[64 + t], qq[t]);
    }
}

// ---------------- output layer: fused BN+residual, 64 -> 2 ----------------
__global__ void __launch_bounds__(256) gemm_out_k(const float* __restrict__ Z,
                                                  const float* __restrict__ W,
                                                  const float* __restrict__ gamma,
                                                  const float* __restrict__ beta,
                                                  const float* __restrict__ st) {
    __shared__ float w0[64], w1[64], ssc[64], ssh[64];
    if (threadIdx.x < 64) {
        int c = threadIdx.x;
        w0[c] = W[c * 2];
        w1[c] = W[c * 2 + 1];
        float s = st[c], q = st[64 + c];
        float m = s * (1.f / NN);
        float v = q * (1.f / NN) - m * m;
        float istd = rsqrtf(v + EPSV);
        float sc = istd * gamma[c];
        ssc[c] = sc;
        ssh[c] = beta[c] - m * sc;
    }
    __syncthreads();
    int warp = threadIdx.x >> 5, lane = threadIdx.x & 31;
    int row = blockIdx.x * 8 + warp;
    if (row >= NN) return;
    const float* zr = Z + (size_t)row * 64;
    const float* hr = (const float*)g_h4 + (size_t)row * 64;
    float h0 = zr[lane]      * ssc[lane]      + ssh[lane]      + hr[lane];
    float h1 = zr[lane + 32] * ssc[lane + 32] + ssh[lane + 32] + hr[lane + 32];
    float a0 = h0 * w0[lane] + h1 * w0[lane + 32];
    float a1 = h0 * w1[lane] + h1 * w1[lane + 32];
    #pragma unroll
    for (int o = 16; o > 0; o >>= 1) {
        a0 += __shfl_down_sync(0xffffffffu, a0, o);
        a1 += __shfl_down_sync(0xffffffffu, a1, o);
    }
    if (lane == 0) g_hw2[row] = make_float2(a0, a1);
}

// fused: CSR aggregation (2 channels) + segment pooling
__global__ void __launch_bounds__(256) csr2_pool_k(const int* __restrict__ bat) {
    __shared__ float sp[NB * OUTD];
    int t = threadIdx.x;
    if (t < NB * OUTD) sp[t] = 0.f;
    __syncthreads();
    int i = blockIdx.x * 256 + t;
    if (i < NN) {
        float d = g_dinv[i];
        float dd = d * d;
        float2 a = g_hw2[i];
        a.x *= dd; a.y *= dd;
        int rs = g_rowptr[i], re = g_rowptr[i + 1];
        int j = rs;
        for (; j + 4 <= re; j += 4) {
            float2 e0 = g_edge[j], e1 = g_edge[j + 1], e2 = g_edge[j + 2], e3 = g_edge[j + 3];
            float2 v0 = g_hw2[__float_as_int(e0.y)];
            float2 v1 = g_hw2[__float_as_int(e1.y)];
            float2 v2 = g_hw2[__float_as_int(e2.y)];
            float2 v3 = g_hw2[__float_as_int(e3.y)];
            a.x += e0.x * v0.x + e1.x * v1.x + e2.x * v2.x + e3.x * v3.x;
            a.y += e0.x * v0.y + e1.x * v1.y + e2.x * v2.y + e3.x * v3.y;
        }
        for (; j < re; ++j) {
            float2 e = g_edge[j];
            float2 v = g_hw2[__float_as_int(e.y)];
            a.x += e.x * v.x; a.y += e.x * v.y;
        }
        int b = bat[i];
        atomicAdd(&sp[2 * b],     a.x);
        atomicAdd(&sp[2 * b + 1], a.y);
    }
    __syncthreads();
    if (t < NB * OUTD) atomicAdd(&g_pool[t], sp[t]);
}

__global__ void final_k(const float* __restrict__ b_out, float* __restrict__ out) {
    int t = threadIdx.x;
    if (t < NB * OUTD) {
        int b = t >> 1, c = t & 1;
        out[t] = g_pool[t] / fmaxf(g_cnt[b], 1.f) + b_out[c];
    }
}

// ---------------- driver ----------------
extern "C" void kernel_launch(void* const* d_in, const int* in_sizes, int n_in,
                              void* d_out, int out_size) {
    const float* x       = (const float*)d_in[0];
    const float* W_in    = (const float*)d_in[1];
    const float* b_in    = (const float*)d_in[2];
    const float* W_h     = (const float*)d_in[3];
    const float* b_h     = (const float*)d_in[4];
    const float* W_out   = (const float*)d_in[5];
    const float* b_out   = (const float*)d_in[6];
    const float* bn_g    = (const float*)d_in[7];
    const float* bn_b    = (const float*)d_in[8];
    const int*   ei      = (const int*)d_in[9];
    const int*   bat     = (const int*)d_in[10];

    float* out = (float*)d_out;

    void *p_z, *p_st;
    cudaGetSymbolAddress(&p_z, g_agg4);
    cudaGetSymbolAddress(&p_st, g_stats);
    float* z  = (float*)p_z;
    float* st = (float*)p_st;   // 3 layers x 128

    // prep
    zero_k<<<391, 256>>>();
    count_k<<<4688, 256>>>(ei, bat);
    scan1_k<<<391, 256>>>();
    scan2_k<<<1, 512>>>();
    scan3_k<<<391, 256>>>();
    scatter_k<<<4688, 256>>>(ei);

    // layer 1: 128 -> 64
    gemm_64<IND, 0><<<1563, 256>>>(x, W_in, nullptr, nullptr, nullptr, NN);
    csr_agg_k<<<6250, 256>>>(b_in, st);

    // layer 2
    gemm_64<HID, 1><<<1563, 256>>>(z, W_h, bn_g, bn_b, st, NN);
    csr_agg_k<<<6250, 256>>>(b_h, st + 128);

    // layer 3
    gemm_64<HID, 2><<<1563, 256>>>(z, W_h + HID * HID, bn_g + HID, bn_b + HID, st + 128, NN);
    csr_agg_k<<<6250, 256>>>(b_h + HID, st + 256);

    // output layer
    gemm_out_k<<<12500, 256>>>(z, W_out, bn_g + 2 * HID, bn_b + 2 * HID, st + 256);
    csr2_pool_k<<<391, 256>>>(bat);
    final_k<<<1, 128>>>(b_out, out);
}

// round 6
// speedup vs baseline: 1.4081x; 1.0346x over previous
#include <cuda_runtime.h>
#include <cuda_fp16.h>

#define NN   100000
#define NE   1200000
#define NB   64
#define HID  64
#define IND  128
#define OUTD 2
#define EPSV 1e-5f

typedef unsigned long long u64;

// ---------------- scratch (static device globals; no allocation) ----------------
__device__ int   g_degi[NN];
__device__ float g_dinv[NN];
__device__ int   g_bsum[391];
__device__ int   g_bsumex[391];
__device__ int   g_rowptr[NN + 1];
__device__ int   g_cur[NN];
__device__ float2 g_edge[NE];          // {coef, src-as-float-bits}
__device__ uint4  g_hwh4[NN * 8];      // h @ W as fp16x8 per uint4 (64 ch/node = 8 uint4)
__device__ float2 g_hw2[NN];           // output-layer hW [N,2] fp32
__device__ float4 g_agg4[NN * 16];     // z buffer (post bias+relu), fp32
__device__ float4 g_h4[NN * 16];       // residual activations, fp32
__device__ float g_stats[3][2 * HID];  // per-layer {sum, sumsq}
__device__ float g_pool[NB * OUTD];
__device__ float g_cnt[NB];

// ---------------- f32x2 helpers ----------------
__device__ __forceinline__ u64 fma2(u64 a, u64 b, u64 c) {
    u64 d;
    asm("fma.rn.f32x2 %0,%1,%2,%3;" : "=l"(d) : "l"(a), "l"(b), "l"(c));
    return d;
}
__device__ __forceinline__ u64 dup2(float x) {
    u64 d;
    asm("mov.b64 %0,{%1,%1};" : "=l"(d) : "f"(x));
    return d;
}

// ---------------- prep ----------------
__global__ void zero_k() {
    int i = blockIdx.x * 256 + threadIdx.x;
    if (i < NN) g_degi[i] = 0;
    if (i < 3 * 2 * HID) ((float*)g_stats)[i] = 0.f;
    if (i < NB * OUTD) g_pool[i] = 0.f;
    if (i < NB) g_cnt[i] = 0.f;
}

__global__ void count_k(const int* __restrict__ ei, const int* __restrict__ bat) {
    int e = blockIdx.x * 256 + threadIdx.x;
    if (e < NE) atomicAdd(&g_degi[ei[NE + e]], 1);
    if (e < NN) atomicAdd(&g_cnt[bat[e]], 1.f);
}

__global__ void scan1_k() {
    __shared__ int sh[256];
    int i = blockIdx.x * 256 + threadIdx.x;
    int d = (i < NN) ? g_degi[i] : 0;
    if (i < NN) g_dinv[i] = rsqrtf((float)d + 1.f);
    sh[threadIdx.x] = d;
    __syncthreads();
    for (int off = 128; off; off >>= 1) {
        if (threadIdx.x < off) sh[threadIdx.x] += sh[threadIdx.x + off];
        __syncthreads();
    }
    if (threadIdx.x == 0) g_bsum[blockIdx.x] = sh[0];
}

__global__ void scan2_k() {
    __shared__ int sh[512];
    int t = threadIdx.x;
    int v = (t < 391) ? g_bsum[t] : 0;
    sh[t] = v;
    __syncthreads();
    for (int off = 1; off < 512; off <<= 1) {
        int a = (t >= off) ? sh[t - off] : 0;
        __syncthreads();
        sh[t] += a;
        __syncthreads();
    }
    if (t < 391) g_bsumex[t] = sh[t] - v;
    if (t == 0) g_rowptr[NN] = NE;
}

__global__ void scan3_k() {
    __shared__ int sh[256];
    int b = blockIdx.x, t = threadIdx.x;
    int i = b * 256 + t;
    int v = (i < NN) ? g_degi[i] : 0;
    sh[t] = v;
    __syncthreads();
    for (int off = 1; off < 256; off <<= 1) {
        int a = (t >= off) ? sh[t - off] : 0;
        __syncthreads();
        sh[t] += a;
        __syncthreads();
    }
    if (i < NN) {
        int rp = g_bsumex[b] + sh[t] - v;
        g_rowptr[i] = rp;
        g_cur[i] = rp;
    }
}

__global__ void scatter_k(const int* __restrict__ ei) {
    int e = blockIdx.x * 256 + threadIdx.x;
    if (e < NE) {
        int s = ei[e], d = ei[NE + e];
        int pos = atomicAdd(&g_cur[d], 1);
        g_edge[pos] = make_float2(g_dinv[s] * g_dinv[d], __int_as_float(s));
    }
}

// ---------------- f32x2 tiled GEMM: hwh[nrows,64](fp16) = Xform(X)[nrows,K] @ W[K,64] ----
// MODE 0: plain; MODE 1: h = X*sc+sh -> g_h4; MODE 2: h = X*sc+sh + g_h4 -> g_h4
template <int K, int MODE>
__global__ void __launch_bounds__(256) gemm_64(const float* __restrict__ X,
                                               const float* __restrict__ W,
                                               const float* __restrict__ gamma,
                                               const float* __restrict__ beta,
                                               const float* __restrict__ st,
                                               int nrows) {
    __shared__ u64  xs2[64][34];
    __shared__ float ws[32][64];
    __shared__ float ssc[64], ssh[64];
    const int tid = threadIdx.x;
    if (MODE > 0) {
        if (tid < 64) {
            float s = st[tid], q = st[64 + tid];
            float m = s * (1.f / NN);
            float v = q * (1.f / NN) - m * m;
            float istd = rsqrtf(v + EPSV);
            float sc = istd * gamma[tid];
            ssc[tid] = sc;
            ssh[tid] = beta[tid] - m * sc;
        }
        __syncthreads();
    }
    const int row0 = blockIdx.x * 64;
    const int tx = tid & 15;
    const int ty = tid >> 4;
    const int c0 = tx * 4;
    const int r0 = ty * 4;
    float* hh = (float*)g_h4;
    u64 acc2[4][2] = {};

    for (int kc = 0; kc < K; kc += 32) {
        #pragma unroll
        for (int it = 0; it < 2; ++it) {
            int row = (tid >> 3) + it * 32;
            int kk  = (tid & 7) * 4;
            float4 v = make_float4(0.f, 0.f, 0.f, 0.f);
            int gr = row0 + row;
            if (gr < nrows) {
                v = *(const float4*)(X + (size_t)gr * K + kc + kk);
                if (MODE > 0) {
                    v.x = v.x * ssc[kc + kk + 0] + ssh[kc + kk + 0];
                    v.y = v.y * ssc[kc + kk + 1] + ssh[kc + kk + 1];
                    v.z = v.z * ssc[kc + kk + 2] + ssh[kc + kk + 2];
                    v.w = v.w * ssc[kc + kk + 3] + ssh[kc + kk + 3];
                    if (MODE == 2) {
                        float4 o = *(const float4*)(hh + (size_t)gr * 64 + kc + kk);
                        v.x += o.x; v.y += o.y; v.z += o.z; v.w += o.w;
                    }
                    *(float4*)(hh + (size_t)gr * 64 + kc + kk) = v;
                }
            }
            xs2[row][kk + 0] = dup2(v.x);
            xs2[row][kk + 1] = dup2(v.y);
            xs2[row][kk + 2] = dup2(v.z);
            xs2[row][kk + 3] = dup2(v.w);
        }
        #pragma unroll
        for (int it = 0; it < 2; ++it) {
            int k  = (tid >> 4) + it * 16;
            int cc = (tid & 15) * 4;
            *(float4*)(&ws[k][cc]) = *(const float4*)(W + (size_t)(kc + k) * 64 + cc);
        }
        __syncthreads();

        #pragma unroll
        for (int k2 = 0; k2 < 16; ++k2) {
            ulonglong2 wa = *(const ulonglong2*)&ws[2 * k2][c0];
            ulonglong2 wb = *(const ulonglong2*)&ws[2 * k2 + 1][c0];
            #pragma unroll
            for (int r = 0; r < 4; ++r) {
                ulonglong2 xk = *(const ulonglong2*)&xs2[r0 + r][2 * k2];
                acc2[r][0] = fma2(xk.x, wa.x, acc2[r][0]);
                acc2[r][1] = fma2(xk.x, wa.y, acc2[r][1]);
                acc2[r][0] = fma2(xk.y, wb.x, acc2[r][0]);
                acc2[r][1] = fma2(xk.y, wb.y, acc2[r][1]);
            }
        }
        __syncthreads();
    }

    #pragma unroll
    for (int r = 0; r < 4; ++r) {
        int gr = row0 + r0 + r;
        if (gr < nrows) {
            float2 a = *(float2*)&acc2[r][0];
            float2 b = *(float2*)&acc2[r][1];
            __half2 p0 = __floats2half2_rn(a.x, a.y);
            __half2 p1 = __floats2half2_rn(b.x, b.y);
            uint2 pk;
            pk.x = *(unsigned int*)&p0;
            pk.y = *(unsigned int*)&p1;
            ((uint2*)g_hwh4)[gr * 16 + tx] = pk;   // row = 16 uint2 = 8 uint4
        }
    }
}

// ---------------- fused CSR aggregation + bias + relu + BN stats ----------------
// 8 lanes per node, each lane owns 8 consecutive channels (one uint4 = fp16x8).
__device__ __forceinline__ void h8acc(uint4 raw, float c,
                                      float4& lo, float4& hi) {
    __half2 a = *(__half2*)&raw.x;
    __half2 b = *(__half2*)&raw.y;
    __half2 d = *(__half2*)&raw.z;
    __half2 e = *(__half2*)&raw.w;
    float2 f0 = __half22float2(a), f1 = __half22float2(b);
    float2 f2 = __half22float2(d), f3 = __half22float2(e);
    lo.x += c * f0.x; lo.y += c * f0.y; lo.z += c * f1.x; lo.w += c * f1.y;
    hi.x += c * f2.x; hi.y += c * f2.y; hi.z += c * f3.x; hi.w += c * f3.y;
}
__device__ __forceinline__ void h8scale(uint4 raw, float c,
                                        float4& lo, float4& hi) {
    __half2 a = *(__half2*)&raw.x;
    __half2 b = *(__half2*)&raw.y;
    __half2 d = *(__half2*)&raw.z;
    __half2 e = *(__half2*)&raw.w;
    float2 f0 = __half22float2(a), f1 = __half22float2(b);
    float2 f2 = __half22float2(d), f3 = __half22float2(e);
    lo = make_float4(c * f0.x, c * f0.y, c * f1.x, c * f1.y);
    hi = make_float4(c * f2.x, c * f2.y, c * f3.x, c * f3.y);
}

__global__ void __launch_bounds__(256) csr_agg_k(const float* __restrict__ bias,
                                                 float* __restrict__ stats) {
    __shared__ float ss[64], qq[64];
    int t = threadIdx.x;
    if (t < 64) { ss[t] = 0.f; qq[t] = 0.f; }
    __syncthreads();

    int idx = blockIdx.x * 256 + t;            // exactly NN*8
    int node = idx >> 3, q = idx & 7;          // q: which uint4 (8 channels)
    int rs = g_rowptr[node], re = g_rowptr[node + 1];
    float d = g_dinv[node];
    float dd = d * d;
    float4 lo, hi;
    h8scale(g_hwh4[idx], dd, lo, hi);          // self-loop term

    int j = rs;
    for (; j + 4 <= re; j += 4) {              // 4-way MLP
        float2 e0 = g_edge[j], e1 = g_edge[j + 1], e2 = g_edge[j + 2], e3 = g_edge[j + 3];
        uint4 v0 = g_hwh4[__float_as_int(e0.y) * 8 + q];
        uint4 v1 = g_hwh4[__float_as_int(e1.y) * 8 + q];
        uint4 v2 = g_hwh4[__float_as_int(e2.y) * 8 + q];
        uint4 v3 = g_hwh4[__float_as_int(e3.y) * 8 + q];
        h8acc(v0, e0.x, lo, hi);
        h8acc(v1, e1.x, lo, hi);
        h8acc(v2, e2.x, lo, hi);
        h8acc(v3, e3.x, lo, hi);
    }
    for (; j < re; ++j) {
        float2 e = g_edge[j];
        h8acc(g_hwh4[__float_as_int(e.y) * 8 + q], e.x, lo, hi);
    }

    float4 blo = ((const float4*)bias)[2 * q];
    float4 bhi = ((const float4*)bias)[2 * q + 1];
    lo.x = fmaxf(lo.x + blo.x, 0.f); lo.y = fmaxf(lo.y + blo.y, 0.f);
    lo.z = fmaxf(lo.z + blo.z, 0.f); lo.w = fmaxf(lo.w + blo.w, 0.f);
    hi.x = fmaxf(hi.x + bhi.x, 0.f); hi.y = fmaxf(hi.y + bhi.y, 0.f);
    hi.z = fmaxf(hi.z + bhi.z, 0.f); hi.w = fmaxf(hi.w + bhi.w, 0.f);
    g_agg4[node * 16 + 2 * q]     = lo;
    g_agg4[node * 16 + 2 * q + 1] = hi;

    // BN stats: lanes l, l+8, l+16, l+24 share the same 8 channels
    float s[8] = {lo.x, lo.y, lo.z, lo.w, hi.x, hi.y, hi.z, hi.w};
    float sq[8];
    #pragma unroll
    for (int k = 0; k < 8; ++k) sq[k] = s[k] * s[k];
    #pragma unroll
    for (int k = 0; k < 8; ++k) {
        s[k]  += __shfl_down_sync(0xffffffffu, s[k], 16);
        sq[k] += __shfl_down_sync(0xffffffffu, sq[k], 16);
        s[k]  += __shfl_down_sync(0xffffffffu, s[k], 8);
        sq[k] += __shfl_down_sync(0xffffffffu, sq[k], 8);
    }
    if ((t & 31) < 8) {
        #pragma unroll
        for (int k = 0; k < 8; ++k) {
            atomicAdd(&ss[8 * q + k], s[k]);
            atomicAdd(&qq[8 * q + k], sq[k]);
        }
    }
    __syncthreads();
    if (t < 64) {
        atomicAdd(&stats[t], ss[t]);
        atomicAdd(&stats[64 + t], qq[t]);
    }
}

// ---------------- output layer: fused BN+residual, 64 -> 2, thread-per-row ----------------
__global__ void __launch_bounds__(256) gemm_out_k(const float* __restrict__ Z,
                                                  const float* __restrict__ W,
                                                  const float* __restrict__ gamma,
                                                  const float* __restrict__ beta,
                                                  const float* __restrict__ st) {
    __shared__ float w0[64], w1[64], ssc[64], ssh[64];
    if (threadIdx.x < 64) {
        int c = threadIdx.x;
        w0[c] = W[c * 2];
        w1[c] = W[c * 2 + 1];
        float s = st[c], q = st[64 + c];
        float m = s * (1.f / NN);
        float v = q * (1.f / NN) - m * m;
        float istd = rsqrtf(v + EPSV);
        float sc = istd * gamma[c];
        ssc[c] = sc;
        ssh[c] = beta[c] - m * sc;
    }
    __syncthreads();
    int row = blockIdx.x * 256 + threadIdx.x;
    if (row >= NN) return;
    const float4* zr = (const float4*)(Z + (size_t)row * 64);
    const float4* hr = (const float4*)((const float*)g_h4 + (size_t)row * 64);
    float a0 = 0.f, a1 = 0.f;
    #pragma unroll
    for (int k4 = 0; k4 < 16; ++k4) {
        float4 z = zr[k4];
        float4 o = hr[k4];
        int c = k4 * 4;
        float h0 = z.x * ssc[c + 0] + ssh[c + 0] + o.x;
        float h1 = z.y * ssc[c + 1] + ssh[c + 1] + o.y;
        float h2 = z.z * ssc[c + 2] + ssh[c + 2] + o.z;
        float h3 = z.w * ssc[c + 3] + ssh[c + 3] + o.w;
        a0 += h0 * w0[c + 0] + h1 * w0[c + 1] + h2 * w0[c + 2] + h3 * w0[c + 3];
        a1 += h0 * w1[c + 0] + h1 * w1[c + 1] + h2 * w1[c + 2] + h3 * w1[c + 3];
    }
    g_hw2[row] = make_float2(a0, a1);
}

// fused: CSR aggregation (2 channels) + segment pooling
__global__ void __launch_bounds__(256) csr2_pool_k(const int* __restrict__ bat) {
    __shared__ float sp[NB * OUTD];
    int t = threadIdx.x;
    if (t < NB * OUTD) sp[t] = 0.f;
    __syncthreads();
    int i = blockIdx.x * 256 + t;
    if (i < NN) {
        float d = g_dinv[i];
        float dd = d * d;
        float2 a = g_hw2[i];
        a.x *= dd; a.y *= dd;
        int rs = g_rowptr[i], re = g_rowptr[i + 1];
        int j = rs;
        for (; j + 4 <= re; j += 4) {
            float2 e0 = g_edge[j], e1 = g_edge[j + 1], e2 = g_edge[j + 2], e3 = g_edge[j + 3];
            float2 v0 = g_hw2[__float_as_int(e0.y)];
            float2 v1 = g_hw2[__float_as_int(e1.y)];
            float2 v2 = g_hw2[__float_as_int(e2.y)];
            float2 v3 = g_hw2[__float_as_int(e3.y)];
            a.x += e0.x * v0.x + e1.x * v1.x + e2.x * v2.x + e3.x * v3.x;
            a.y += e0.x * v0.y + e1.x * v1.y + e2.x * v2.y + e3.x * v3.y;
        }
        for (; j < re; ++j) {
            float2 e = g_edge[j];
            float2 v = g_hw2[__float_as_int(e.y)];
            a.x += e.x * v.x; a.y += e.x * v.y;
        }
        int b = bat[i];
        atomicAdd(&sp[2 * b],     a.x);
        atomicAdd(&sp[2 * b + 1], a.y);
    }
    __syncthreads();
    if (t < NB * OUTD) atomicAdd(&g_pool[t], sp[t]);
}

__global__ void final_k(const float* __restrict__ b_out, float* __restrict__ out) {
    int t = threadIdx.x;
    if (t < NB * OUTD) {
        int b = t >> 1, c = t & 1;
        out[t] = g_pool[t] / fmaxf(g_cnt[b], 1.f) + b_out[c];
    }
}

// ---------------- driver ----------------
extern "C" void kernel_launch(void* const* d_in, const int* in_sizes, int n_in,
                              void* d_out, int out_size) {
    const float* x       = (const float*)d_in[0];
    const float* W_in    = (const float*)d_in[1];
    const float* b_in    = (const float*)d_in[2];
    const float* W_h     = (const float*)d_in[3];
    const float* b_h     = (const float*)d_in[4];
    const float* W_out   = (const float*)d_in[5];
    const float* b_out   = (const float*)d_in[6];
    const float* bn_g    = (const float*)d_in[7];
    const float* bn_b    = (const float*)d_in[8];
    const int*   ei      = (const int*)d_in[9];
    const int*   bat     = (const int*)d_in[10];

    float* out = (float*)d_out;

    void *p_z, *p_st;
    cudaGetSymbolAddress(&p_z, g_agg4);
    cudaGetSymbolAddress(&p_st, g_stats);
    float* z  = (float*)p_z;
    float* st = (float*)p_st;   // 3 layers x 128

    // prep
    zero_k<<<391, 256>>>();
    count_k<<<4688, 256>>>(ei, bat);
    scan1_k<<<391, 256>>>();
    scan2_k<<<1, 512>>>();
    scan3_k<<<391, 256>>>();
    scatter_k<<<4688, 256>>>(ei);

    // layer 1: 128 -> 64
    gemm_64<IND, 0><<<1563, 256>>>(x, W_in, nullptr, nullptr, nullptr, NN);
    csr_agg_k<<<3125, 256>>>(b_in, st);

    // layer 2
    gemm_64<HID, 1><<<1563, 256>>>(z, W_h, bn_g, bn_b, st, NN);
    csr_agg_k<<<3125, 256>>>(b_h, st + 128);

    // layer 3
    gemm_64<HID, 2><<<1563, 256>>>(z, W_h + HID * HID, bn_g + HID, bn_b + HID, st + 128, NN);
    csr_agg_k<<<3125, 256>>>(b_h + HID, st + 256);

    // output layer
    gemm_out_k<<<391, 256>>>(z, W_out, bn_g + 2 * HID, bn_b + 2 * HID, st + 256);
    csr2_pool_k<<<391, 256>>>(bat);
    final_k<<<1, 128>>>(b_out, out);
}

// round 7
// speedup vs baseline: 1.5138x; 1.0751x over previous
#include <cuda_runtime.h>
#include <cuda_fp16.h>

#define NN   100000
#define NE   1200000
#define NB   64
#define HID  64
#define IND  128
#define OUTD 2
#define EPSV 1e-5f

// ---------------- scratch (static device globals; no allocation) ----------------
__device__ int   g_degi[NN];
__device__ float g_dinv[NN];
__device__ int   g_bsum[391];
__device__ int   g_rowptr[NN + 1];
__device__ int   g_cur[NN];
__device__ float2 g_edge[NE];          // {coef, src-as-float-bits}
__device__ uint4  g_hwh4[NN * 8];      // h @ W as fp16x8 per uint4 (64 ch/node)
__device__ float2 g_hw2[NN];           // output-layer hW [N,2] fp32
__device__ float4 g_agg4[NN * 16];     // z buffer (post bias+relu), fp32
__device__ float4 g_h4[NN * 16];       // residual activations, fp32
__device__ float g_stats[3][2 * HID];  // per-layer {sum, sumsq}
__device__ float g_pool[NB * OUTD];
__device__ float g_cnt[NB];

// ---------------- prep ----------------
__global__ void zero_k() {
    int i = blockIdx.x * 256 + threadIdx.x;
    if (i < NN) g_degi[i] = 0;
    if (i < 3 * 2 * HID) ((float*)g_stats)[i] = 0.f;
    if (i < NB * OUTD) g_pool[i] = 0.f;
    if (i < NB) g_cnt[i] = 0.f;
    if (i == 0) g_rowptr[NN] = NE;
}

__global__ void count_k(const int* __restrict__ ei, const int* __restrict__ bat) {
    int e = blockIdx.x * 256 + threadIdx.x;
    if (e < NE) atomicAdd(&g_degi[ei[NE + e]], 1);
    if (e < NN) atomicAdd(&g_cnt[bat[e]], 1.f);
}

__global__ void scan1_k() {
    __shared__ int sh[256];
    int i = blockIdx.x * 256 + threadIdx.x;
    int d = (i < NN) ? g_degi[i] : 0;
    if (i < NN) g_dinv[i] = rsqrtf((float)d + 1.f);
    sh[threadIdx.x] = d;
    __syncthreads();
    for (int off = 128; off; off >>= 1) {
        if (threadIdx.x < off) sh[threadIdx.x] += sh[threadIdx.x + off];
        __syncthreads();
    }
    if (threadIdx.x == 0) g_bsum[blockIdx.x] = sh[0];
}

// merged block-prefix + local scan
__global__ void scan23_k() {
    __shared__ int sh[256];
    __shared__ int base_sh;
    int b = blockIdx.x, t = threadIdx.x;
    int part = 0;
    for (int i = t; i < b; i += 256) part += g_bsum[i];
    sh[t] = part;
    __syncthreads();
    for (int off = 128; off; off >>= 1) {
        if (t < off) sh[t] += sh[t + off];
        __syncthreads();
    }
    if (t == 0) base_sh = sh[0];
    __syncthreads();
    int base = base_sh;
    __syncthreads();
    int i = b * 256 + t;
    int v = (i < NN) ? g_degi[i] : 0;
    sh[t] = v;
    __syncthreads();
    for (int off = 1; off < 256; off <<= 1) {
        int a = (t >= off) ? sh[t - off] : 0;
        __syncthreads();
        sh[t] += a;
        __syncthreads();
    }
    if (i < NN) {
        int rp = base + sh[t] - v;
        g_rowptr[i] = rp;
        g_cur[i] = rp;
    }
}

__global__ void scatter_k(const int* __restrict__ ei) {
    int e = blockIdx.x * 256 + threadIdx.x;
    if (e < NE) {
        int s = ei[e], d = ei[NE + e];
        int pos = atomicAdd(&g_cur[d], 1);
        g_edge[pos] = make_float2(g_dinv[s] * g_dinv[d], __int_as_float(s));
    }
}

// ---------------- HMMA GEMM: hwh[nrows,64](fp16) = Xform(X)[nrows,K] @ W[K,64] ----
// MODE 0: plain; MODE 1: h = X*sc+sh -> g_h4; MODE 2: h = X*sc+sh + g_h4 -> g_h4
// Block: 256 threads (8 warps), tile 128 rows x 64 cols, K staged in 64-chunks.
#define XPAD 72
template <int K, int MODE>
__global__ void __launch_bounds__(256) gemm_hmma(const float* __restrict__ X,
                                                 const float* __restrict__ W,
                                                 const float* __restrict__ gamma,
                                                 const float* __restrict__ beta,
                                                 const float* __restrict__ st,
                                                 int nrows) {
    __shared__ __half Xs[128][XPAD];
    __shared__ __half Ws[64][XPAD];
    __shared__ float ssc[64], ssh[64];
    const int tid = threadIdx.x;
    if (MODE > 0) {
        if (tid < 64) {
            float s = st[tid], q = st[64 + tid];
            float m = s * (1.f / NN);
            float v = q * (1.f / NN) - m * m;
            float istd = rsqrtf(v + EPSV);
            float sc = istd * gamma[tid];
            ssc[tid] = sc;
            ssh[tid] = beta[tid] - m * sc;
        }
        __syncthreads();
    }
    const int row0 = blockIdx.x * 128;
    const int warp = tid >> 5, lane = tid & 31;
    float acc[8][4] = {};
    float* hh = (float*)g_h4;

    for (int kc = 0; kc < K; kc += 64) {
        // stage X: 128 rows x 64 k (fp32 -> fp16, optional BN+residual transform)
        {
            int row = tid >> 1;
            int k0 = (tid & 1) * 32;
            int gr = row0 + row;
            #pragma unroll
            for (int i = 0; i < 8; ++i) {
                float4 v = make_float4(0.f, 0.f, 0.f, 0.f);
                if (gr < nrows) {
                    int c = kc + k0 + i * 4;
                    v = *(const float4*)(X + (size_t)gr * K + c);
                    if (MODE > 0) {
                        v.x = v.x * ssc[c + 0] + ssh[c + 0];
                        v.y = v.y * ssc[c + 1] + ssh[c + 1];
                        v.z = v.z * ssc[c + 2] + ssh[c + 2];
                        v.w = v.w * ssc[c + 3] + ssh[c + 3];
                        if (MODE == 2) {
                            float4 o = *(const float4*)(hh + (size_t)gr * 64 + c);
                            v.x += o.x; v.y += o.y; v.z += o.z; v.w += o.w;
                        }
                        *(float4*)(hh + (size_t)gr * 64 + c) = v;
                    }
                }
                *(__half2*)&Xs[row][k0 + i * 4]     = __floats2half2_rn(v.x, v.y);
                *(__half2*)&Xs[row][k0 + i * 4 + 2] = __floats2half2_rn(v.z, v.w);
            }
        }
        // stage W: 64 k-rows x 64 cols
        {
            int r = tid >> 2;
            int c0 = (tid & 3) * 16;
            #pragma unroll
            for (int i = 0; i < 4; ++i) {
                float4 v = *(const float4*)(W + (size_t)(kc + r) * 64 + c0 + i * 4);
                *(__half2*)&Ws[r][c0 + i * 4]     = __floats2half2_rn(v.x, v.y);
                *(__half2*)&Ws[r][c0 + i * 4 + 2] = __floats2half2_rn(v.z, v.w);
            }
        }
        __syncthreads();

        int r0 = warp * 16;
        #pragma unroll
        for (int k16 = 0; k16 < 64; k16 += 16) {
            unsigned a0, a1, a2, a3;
            {
                const __half* pa = &Xs[r0 + (lane & 15)][k16 + (lane >> 4) * 8];
                unsigned addr = (unsigned)__cvta_generic_to_shared(pa);
                asm volatile("ldmatrix.sync.aligned.m8n8.x4.shared.b16 {%0,%1,%2,%3},[%4];"
                             : "=r"(a0), "=r"(a1), "=r"(a2), "=r"(a3) : "r"(addr));
            }
            #pragma unroll
            for (int nb = 0; nb < 4; ++nb) {
                int c = nb * 16;
                unsigned b0, b1, b2, b3;
                const __half* pb = &Ws[k16 + (lane & 15)][c + (lane >> 4) * 8];
                unsigned addr = (unsigned)__cvta_generic_to_shared(pb);
                asm volatile("ldmatrix.sync.aligned.m8n8.x4.trans.shared.b16 {%0,%1,%2,%3},[%4];"
                             : "=r"(b0), "=r"(b1), "=r"(b2), "=r"(b3) : "r"(addr));
                asm volatile("mma.sync.aligned.m16n8k16.row.col.f32.f16.f16.f32 "
                             "{%0,%1,%2,%3},{%4,%5,%6,%7},{%8,%9},{%0,%1,%2,%3};"
                             : "+f"(acc[2 * nb][0]), "+f"(acc[2 * nb][1]),
                               "+f"(acc[2 * nb][2]), "+f"(acc[2 * nb][3])
                             : "r"(a0), "r"(a1), "r"(a2), "r"(a3), "r"(b0), "r"(b1));
                asm volatile("mma.sync.aligned.m16n8k16.row.col.f32.f16.f16.f32 "
                             "{%0,%1,%2,%3},{%4,%5,%6,%7},{%8,%9},{%0,%1,%2,%3};"
                             : "+f"(acc[2 * nb + 1][0]), "+f"(acc[2 * nb + 1][1]),
                               "+f"(acc[2 * nb + 1][2]), "+f"(acc[2 * nb + 1][3])
                             : "r"(a0), "r"(a1), "r"(a2), "r"(a3), "r"(b2), "r"(b3));
            }
        }
        __syncthreads();
    }

    // epilogue: fp16 pack + store. c0,c1 -> (row lane>>2, cols 2(lane&3)); c2,c3 -> row+8
    unsigned* outp = (unsigned*)g_hwh4;
    int gr0 = row0 + warp * 16 + (lane >> 2);
    #pragma unroll
    for (int nb = 0; nb < 8; ++nb) {
        __half2 lo = __floats2half2_rn(acc[nb][0], acc[nb][1]);
        __half2 hi = __floats2half2_rn(acc[nb][2], acc[nb][3]);
        int ci = nb * 4 + (lane & 3);
        if (gr0 < nrows)     outp[(size_t)gr0 * 32 + ci]       = *(unsigned*)&lo;
        if (gr0 + 8 < nrows) outp[(size_t)(gr0 + 8) * 32 + ci] = *(unsigned*)&hi;
    }
}

// ---------------- fused CSR aggregation + bias + relu + BN stats ----------------
__device__ __forceinline__ void h8acc(uint4 raw, float c, float4& lo, float4& hi) {
    __half2 a = *(__half2*)&raw.x;
    __half2 b = *(__half2*)&raw.y;
    __half2 d = *(__half2*)&raw.z;
    __half2 e = *(__half2*)&raw.w;
    float2 f0 = __half22float2(a), f1 = __half22float2(b);
    float2 f2 = __half22float2(d), f3 = __half22float2(e);
    lo.x += c * f0.x; lo.y += c * f0.y; lo.z += c * f1.x; lo.w += c * f1.y;
    hi.x += c * f2.x; hi.y += c * f2.y; hi.z += c * f3.x; hi.w += c * f3.y;
}
__device__ __forceinline__ void h8scale(uint4 raw, float c, float4& lo, float4& hi) {
    __half2 a = *(__half2*)&raw.x;
    __half2 b = *(__half2*)&raw.y;
    __half2 d = *(__half2*)&raw.z;
    __half2 e = *(__half2*)&raw.w;
    float2 f0 = __half22float2(a), f1 = __half22float2(b);
    float2 f2 = __half22float2(d), f3 = __half22float2(e);
    lo = make_float4(c * f0.x, c * f0.y, c * f1.x, c * f1.y);
    hi = make_float4(c * f2.x, c * f2.y, c * f3.x, c * f3.y);
}

__global__ void __launch_bounds__(256) csr_agg_k(const float* __restrict__ bias,
                                                 float* __restrict__ stats) {
    __shared__ float ss[64], qq[64];
    int t = threadIdx.x;
    if (t < 64) { ss[t] = 0.f; qq[t] = 0.f; }
    __syncthreads();

    int idx = blockIdx.x * 256 + t;            // exactly NN*8
    int node = idx >> 3, q = idx & 7;
    int rs = g_rowptr[node], re = g_rowptr[node + 1];
    float d = g_dinv[node];
    float dd = d * d;
    float4 lo, hi;
    h8scale(g_hwh4[idx], dd, lo, hi);

    int j = rs;
    for (; j + 4 <= re; j += 4) {
        float2 e0 = g_edge[j], e1 = g_edge[j + 1], e2 = g_edge[j + 2], e3 = g_edge[j + 3];
        uint4 v0 = g_hwh4[__float_as_int(e0.y) * 8 + q];
        uint4 v1 = g_hwh4[__float_as_int(e1.y) * 8 + q];
        uint4 v2 = g_hwh4[__float_as_int(e2.y) * 8 + q];
        uint4 v3 = g_hwh4[__float_as_int(e3.y) * 8 + q];
        h8acc(v0, e0.x, lo, hi);
        h8acc(v1, e1.x, lo, hi);
        h8acc(v2, e2.x, lo, hi);
        h8acc(v3, e3.x, lo, hi);
    }
    for (; j < re; ++j) {
        float2 e = g_edge[j];
        h8acc(g_hwh4[__float_as_int(e.y) * 8 + q], e.x, lo, hi);
    }

    float4 blo = ((const float4*)bias)[2 * q];
    float4 bhi = ((const float4*)bias)[2 * q + 1];
    lo.x = fmaxf(lo.x + blo.x, 0.f); lo.y = fmaxf(lo.y + blo.y, 0.f);
    lo.z = fmaxf(lo.z + blo.z, 0.f); lo.w = fmaxf(lo.w + blo.w, 0.f);
    hi.x = fmaxf(hi.x + bhi.x, 0.f); hi.y = fmaxf(hi.y + bhi.y, 0.f);
    hi.z = fmaxf(hi.z + bhi.z, 0.f); hi.w = fmaxf(hi.w + bhi.w, 0.f);
    g_agg4[node * 16 + 2 * q]     = lo;
    g_agg4[node * 16 + 2 * q + 1] = hi;

    float s[8] = {lo.x, lo.y, lo.z, lo.w, hi.x, hi.y, hi.z, hi.w};
    float sq[8];
    #pragma unroll
    for (int k = 0; k < 8; ++k) sq[k] = s[k] * s[k];
    #pragma unroll
    for (int k = 0; k < 8; ++k) {
        s[k]  += __shfl_down_sync(0xffffffffu, s[k], 16);
        sq[k] += __shfl_down_sync(0xffffffffu, sq[k], 16);
        s[k]  += __shfl_down_sync(0xffffffffu, s[k], 8);
        sq[k] += __shfl_down_sync(0xffffffffu, sq[k], 8);
    }
    if ((t & 31) < 8) {
        #pragma unroll
        for (int k = 0; k < 8; ++k) {
            atomicAdd(&ss[8 * q + k], s[k]);
            atomicAdd(&qq[8 * q + k], sq[k]);
        }
    }
    __syncthreads();
    if (t < 64) {
        atomicAdd(&stats[t], ss[t]);
        atomicAdd(&stats[64 + t], qq[t]);
    }
}

// ---------------- output layer: fused BN+residual, 64 -> 2, thread-per-row ----------------
__global__ void __launch_bounds__(256) gemm_out_k(const float* __restrict__ Z,
                                                  const float* __restrict__ W,
                                                  const float* __restrict__ gamma,
                                                  const float* __restrict__ beta,
                                                  const float* __restrict__ st) {
    __shared__ float w0[64], w1[64], ssc[64], ssh[64];
    if (threadIdx.x < 64) {
        int c = threadIdx.x;
        w0[c] = W[c * 2];
        w1[c] = W[c * 2 + 1];
        float s = st[c], q = st[64 + c];
        float m = s * (1.f / NN);
        float v = q * (1.f / NN) - m * m;
        float istd = rsqrtf(v + EPSV);
        float sc = istd * gamma[c];
        ssc[c] = sc;
        ssh[c] = beta[c] - m * sc;
    }
    __syncthreads();
    int row = blockIdx.x * 256 + threadIdx.x;
    if (row >= NN) return;
    const float4* zr = (const float4*)(Z + (size_t)row * 64);
    const float4* hr = (const float4*)((const float*)g_h4 + (size_t)row * 64);
    float a0 = 0.f, a1 = 0.f;
    #pragma unroll
    for (int k4 = 0; k4 < 16; ++k4) {
        float4 z = zr[k4];
        float4 o = hr[k4];
        int c = k4 * 4;
        float h0 = z.x * ssc[c + 0] + ssh[c + 0] + o.x;
        float h1 = z.y * ssc[c + 1] + ssh[c + 1] + o.y;
        float h2 = z.z * ssc[c + 2] + ssh[c + 2] + o.z;
        float h3 = z.w * ssc[c + 3] + ssh[c + 3] + o.w;
        a0 += h0 * w0[c + 0] + h1 * w0[c + 1] + h2 * w0[c + 2] + h3 * w0[c + 3];
        a1 += h0 * w1[c + 0] + h1 * w1[c + 1] + h2 * w1[c + 2] + h3 * w1[c + 3];
    }
    g_hw2[row] = make_float2(a0, a1);
}

// fused: CSR aggregation (2 channels) + segment pooling
__global__ void __launch_bounds__(256) csr2_pool_k(const int* __restrict__ bat) {
    __shared__ float sp[NB * OUTD];
    int t = threadIdx.x;
    if (t < NB * OUTD) sp[t] = 0.f;
    __syncthreads();
    int i = blockIdx.x * 256 + t;
    if (i < NN) {
        float d = g_dinv[i];
        float dd = d * d;
        float2 a = g_hw2[i];
        a.x *= dd; a.y *= dd;
        int rs = g_rowptr[i], re = g_rowptr[i + 1];
        int j = rs;
        for (; j + 4 <= re; j += 4) {
            float2 e0 = g_edge[j], e1 = g_edge[j + 1], e2 = g_edge[j + 2], e3 = g_edge[j + 3];
            float2 v0 = g_hw2[__float_as_int(e0.y)];
            float2 v1 = g_hw2[__float_as_int(e1.y)];
            float2 v2 = g_hw2[__float_as_int(e2.y)];
            float2 v3 = g_hw2[__float_as_int(e3.y)];
            a.x += e0.x * v0.x + e1.x * v1.x + e2.x * v2.x + e3.x * v3.x;
            a.y += e0.x * v0.y + e1.x * v1.y + e2.x * v2.y + e3.x * v3.y;
        }
        for (; j < re; ++j) {
            float2 e = g_edge[j];
            float2 v = g_hw2[__float_as_int(e.y)];
            a.x += e.x * v.x; a.y += e.x * v.y;
        }
        int b = bat[i];
        atomicAdd(&sp[2 * b],     a.x);
        atomicAdd(&sp[2 * b + 1], a.y);
    }
    __syncthreads();
    if (t < NB * OUTD) atomicAdd(&g_pool[t], sp[t]);
}

__global__ void final_k(const float* __restrict__ b_out, float* __restrict__ out) {
    int t = threadIdx.x;
    if (t < NB * OUTD) {
        int b = t >> 1, c = t & 1;
        out[t] = g_pool[t] / fmaxf(g_cnt[b], 1.f) + b_out[c];
    }
}

// ---------------- driver ----------------
extern "C" void kernel_launch(void* const* d_in, const int* in_sizes, int n_in,
                              void* d_out, int out_size) {
    const float* x       = (const float*)d_in[0];
    const float* W_in    = (const float*)d_in[1];
    const float* b_in    = (const float*)d_in[2];
    const float* W_h     = (const float*)d_in[3];
    const float* b_h     = (const float*)d_in[4];
    const float* W_out   = (const float*)d_in[5];
    const float* b_out   = (const float*)d_in[6];
    const float* bn_g    = (const float*)d_in[7];
    const float* bn_b    = (const float*)d_in[8];
    const int*   ei      = (const int*)d_in[9];
    const int*   bat     = (const int*)d_in[10];

    float* out = (float*)d_out;

    void *p_z, *p_st;
    cudaGetSymbolAddress(&p_z, g_agg4);
    cudaGetSymbolAddress(&p_st, g_stats);
    float* z  = (float*)p_z;
    float* st = (float*)p_st;   // 3 layers x 128

    // prep (5 launches)
    zero_k<<<391, 256>>>();
    count_k<<<4688, 256>>>(ei, bat);
    scan1_k<<<391, 256>>>();
    scan23_k<<<391, 256>>>();
    scatter_k<<<4688, 256>>>(ei);

    // layer 1: 128 -> 64   (launch #6 — ncu capture slot)
    gemm_hmma<IND, 0><<<782, 256>>>(x, W_in, nullptr, nullptr, nullptr, NN);
    csr_agg_k<<<3125, 256>>>(b_in, st);

    // layer 2
    gemm_hmma<HID, 1><<<782, 256>>>(z, W_h, bn_g, bn_b, st, NN);
    csr_agg_k<<<3125, 256>>>(b_h, st + 128);

    // layer 3
    gemm_hmma<HID, 2><<<782, 256>>>(z, W_h + HID * HID, bn_g + HID, bn_b + HID, st + 128, NN);
    csr_agg_k<<<3125, 256>>>(b_h + HID, st + 256);

    // output layer
    gemm_out_k<<<391, 256>>>(z, W_out, bn_g + 2 * HID, bn_b + 2 * HID, st + 256);
    csr2_pool_k<<<391, 256>>>(bat);
    final_k<<<1, 128>>>(b_out, out);
}